// round 1
// baseline (speedup 1.0000x reference)
#include <cuda_runtime.h>
#include <math.h>

#define D_MODEL 2048
#define NH 32
#define NKV 8
#define HD 64
#define BATCH 2
#define SEQ 2048
#define TOK (BATCH * SEQ)   // 4096

// ---------------- scratch (device globals; no allocation allowed) ----------
__device__ float g_q[(size_t)TOK * NH * HD];    // 33.5 MB
__device__ float g_k[(size_t)TOK * NKV * HD];   //  8.4 MB
__device__ float g_v[(size_t)TOK * NKV * HD];   //  8.4 MB
__device__ float g_o[(size_t)TOK * NH * HD];    // 33.5 MB

// ---------------- SGEMM: C[M,N] = A[M,K] @ B[K,N], all row-major ----------
// BM=BN=128, BK=8, 256 threads, 8x8 per-thread microtile.
// M=4096, N in {512,2048}, K=2048 -> all tiles exact, no bounds checks.
#define BM 128
#define BN 128
#define BK 8
#define TM 8
#define TN 8

__global__ __launch_bounds__(256) void sgemm_kernel(
    const float* __restrict__ A, const float* __restrict__ Bm,
    float* __restrict__ C, int M, int N, int K)
{
    __shared__ float As[BK][BM];
    __shared__ float Bs[BK][BN];

    const int tid = threadIdx.x;
    const int brow = blockIdx.y, bcol = blockIdx.x;
    const int tx = tid & 15, ty = tid >> 4;

    // A tile loader: 128x8 floats, one float4 per thread along K
    const int arow = tid >> 1;
    const int acol = (tid & 1) << 2;
    // B tile loader: 8x128, one float4 per thread along N
    const int brow_i = tid >> 5;
    const int bcol_i = (tid & 31) << 2;

    const float* Ap = A + (size_t)(brow * BM) * K;
    const float* Bp = Bm + bcol * BN;

    float acc[TM][TN];
#pragma unroll
    for (int i = 0; i < TM; i++)
#pragma unroll
        for (int j = 0; j < TN; j++) acc[i][j] = 0.0f;

    for (int k0 = 0; k0 < K; k0 += BK) {
        float4 a4 = *(const float4*)(Ap + (size_t)arow * K + k0 + acol);
        As[acol + 0][arow] = a4.x;
        As[acol + 1][arow] = a4.y;
        As[acol + 2][arow] = a4.z;
        As[acol + 3][arow] = a4.w;
        float4 b4 = *(const float4*)(Bp + (size_t)(k0 + brow_i) * N + bcol_i);
        *(float4*)&Bs[brow_i][bcol_i] = b4;
        __syncthreads();

#pragma unroll
        for (int kk = 0; kk < BK; kk++) {
            float ra[TM], rb[TN];
            *(float4*)&ra[0] = *(const float4*)&As[kk][ty * TM];
            *(float4*)&ra[4] = *(const float4*)&As[kk][ty * TM + 4];
            *(float4*)&rb[0] = *(const float4*)&Bs[kk][tx * TN];
            *(float4*)&rb[4] = *(const float4*)&Bs[kk][tx * TN + 4];
#pragma unroll
            for (int i = 0; i < TM; i++)
#pragma unroll
                for (int j = 0; j < TN; j++) acc[i][j] += ra[i] * rb[j];
        }
        __syncthreads();
    }

    float* Cp = C + (size_t)(brow * BM + ty * TM) * N + bcol * BN + tx * TN;
#pragma unroll
    for (int i = 0; i < TM; i++) {
        *(float4*)(Cp + (size_t)i * N) =
            make_float4(acc[i][0], acc[i][1], acc[i][2], acc[i][3]);
        *(float4*)(Cp + (size_t)i * N + 4) =
            make_float4(acc[i][4], acc[i][5], acc[i][6], acc[i][7]);
    }
}

// ---------------- RoPE + per-head RMSNorm (one warp per (token, head)) ----
__global__ void rope_rms_kernel(float* __restrict__ buf,
                                const float* __restrict__ cosp,
                                const float* __restrict__ sinp,
                                int nheads)
{
    int gw = (blockIdx.x * blockDim.x + threadIdx.x) >> 5;
    int lane = threadIdx.x & 31;
    int total = TOK * nheads;
    if (gw >= total) return;
    int tok = gw / nheads;       // b*SEQ + l
    int l = tok % SEQ;

    float* p = buf + (size_t)gw * HD;
    float x1 = p[lane];
    float x2 = p[lane + 32];
    float c = cosp[l * 32 + lane];
    float s = sinp[l * 32 + lane];
    float o1 = x1 * c - x2 * s;
    float o2 = x2 * c + x1 * s;
    float ss = o1 * o1 + o2 * o2;
#pragma unroll
    for (int off = 16; off > 0; off >>= 1)
        ss += __shfl_xor_sync(0xffffffffu, ss, off);
    float r = rsqrtf(ss * (1.0f / 64.0f) + 1e-6f);
    p[lane] = o1 * r;
    p[lane + 32] = o2 * r;
}

// ---------------- Flash attention, fp32, causal, GQA ----------------------
// Block: 256 threads (8 warps). Each block: one (batch b, head h, 64-query tile).
// Each warp owns 8 query rows; lanes own keys {lane, lane+32} within the tile.
// SMEM: Qs[64][64], Ks[64][68], Vs[64][68] (pad 68 -> conflict-free LDS.128),
//       ps[8 warps][8 rows][64 keys].
#define KS_STRIDE 68
#define ATTN_QS   (64 * 64)
#define ATTN_KS   (64 * KS_STRIDE)
#define ATTN_PS   (8 * 8 * 64)
#define ATTN_SMEM ((ATTN_QS + 2 * ATTN_KS + ATTN_PS) * 4)   // 67584 bytes

__global__ __launch_bounds__(256) void attn_kernel()
{
    extern __shared__ float sm[];
    float* Qs = sm;                       // [64][64]
    float* Ks = Qs + ATTN_QS;             // [64][68]
    float* Vs = Ks + ATTN_KS;             // [64][68]
    float* ps = Vs + ATTN_KS;             // [8][8][64]

    const int qt = blockIdx.x;            // query tile (0..31)
    const int h = blockIdx.y;             // head (0..31)
    const int b = blockIdx.z;             // batch
    const int kvh = h >> 2;               // GQA: 4 q heads per kv head
    const int tid = threadIdx.x;
    const int warp = tid >> 5;
    const int lane = tid & 31;
    const int q0 = qt * 64;

    // load Q tile (row-major [64][64])
#pragma unroll
    for (int it = 0; it < 4; it++) {
        int i = tid + it * 256;           // 0..1023
        int r = i >> 4, d4 = (i & 15) << 2;
        const float* qp = g_q + (((size_t)(b * SEQ + q0 + r) * NH + h) << 6) + d4;
        *(float4*)(Qs + r * 64 + d4) = *(const float4*)qp;
    }

    float m[8], lsum[8], acc0[8], acc1[8];
#pragma unroll
    for (int r = 0; r < 8; r++) {
        m[r] = -1e30f; lsum[r] = 0.0f; acc0[r] = 0.0f; acc1[r] = 0.0f;
    }
    const float scale = 0.125f;           // rsqrt(64)
    float* psw = ps + warp * (8 * 64);

    for (int kt = 0; kt <= qt; kt++) {
        __syncthreads();                  // protect Ks/Vs (and Qs on 1st iter)
        const int k0 = kt * 64;
#pragma unroll
        for (int it = 0; it < 4; it++) {
            int i = tid + it * 256;
            int r = i >> 4, d4 = (i & 15) << 2;
            size_t gi = (((size_t)(b * SEQ + k0 + r) * NKV + kvh) << 6) + d4;
            float4 k4 = *(const float4*)(g_k + gi);
            float4 v4 = *(const float4*)(g_v + gi);
            *(float4*)(Ks + r * KS_STRIDE + d4) = k4;
            *(float4*)(Vs + r * KS_STRIDE + d4) = v4;
        }
        __syncthreads();

        // ---- scores: s[rr][2 keys] over d, chunked by 8 ----
        float s0[8], s1[8];
#pragma unroll
        for (int r = 0; r < 8; r++) { s0[r] = 0.0f; s1[r] = 0.0f; }

        const float* ka_base = Ks + lane * KS_STRIDE;
        const float* kb_base = Ks + (lane + 32) * KS_STRIDE;
#pragma unroll
        for (int d0 = 0; d0 < 64; d0 += 8) {
            float4 ka0 = *(const float4*)(ka_base + d0);
            float4 ka1 = *(const float4*)(ka_base + d0 + 4);
            float4 kb0 = *(const float4*)(kb_base + d0);
            float4 kb1 = *(const float4*)(kb_base + d0 + 4);
#pragma unroll
            for (int rr = 0; rr < 8; rr++) {
                const float* qp = Qs + (warp * 8 + rr) * 64 + d0;
                float4 qa = *(const float4*)qp;
                float4 qb = *(const float4*)(qp + 4);
                s0[rr] += qa.x * ka0.x + qa.y * ka0.y + qa.z * ka0.z + qa.w * ka0.w
                        + qb.x * ka1.x + qb.y * ka1.y + qb.z * ka1.z + qb.w * ka1.w;
                s1[rr] += qa.x * kb0.x + qa.y * kb0.y + qa.z * kb0.z + qa.w * kb0.w
                        + qb.x * kb1.x + qb.y * kb1.y + qb.z * kb1.z + qb.w * kb1.w;
            }
        }

        // ---- online softmax per row ----
        const bool diag = (kt == qt);
#pragma unroll
        for (int rr = 0; rr < 8; rr++) {
            int qi = q0 + warp * 8 + rr;
            float v0 = s0[rr] * scale;
            float v1 = s1[rr] * scale;
            if (diag) {
                if (k0 + lane > qi) v0 = -1e30f;
                if (k0 + lane + 32 > qi) v1 = -1e30f;
            }
            float mx = fmaxf(v0, v1);
#pragma unroll
            for (int off = 16; off > 0; off >>= 1)
                mx = fmaxf(mx, __shfl_xor_sync(0xffffffffu, mx, off));
            float mnew = fmaxf(m[rr], mx);
            float p0 = __expf(v0 - mnew);
            float p1 = __expf(v1 - mnew);
            float corr = __expf(m[rr] - mnew);
            m[rr] = mnew;
            float pr = p0 + p1;
#pragma unroll
            for (int off = 16; off > 0; off >>= 1)
                pr += __shfl_xor_sync(0xffffffffu, pr, off);
            lsum[rr] = lsum[rr] * corr + pr;
            acc0[rr] *= corr;
            acc1[rr] *= corr;
            psw[rr * 64 + lane] = p0;
            psw[rr * 64 + lane + 32] = p1;
        }
        __syncwarp();

        // ---- PV accumulation, j chunked by 4 ----
#pragma unroll
        for (int j0 = 0; j0 < 64; j0 += 4) {
            float v00 = Vs[(j0 + 0) * KS_STRIDE + lane];
            float v01 = Vs[(j0 + 0) * KS_STRIDE + lane + 32];
            float v10 = Vs[(j0 + 1) * KS_STRIDE + lane];
            float v11 = Vs[(j0 + 1) * KS_STRIDE + lane + 32];
            float v20 = Vs[(j0 + 2) * KS_STRIDE + lane];
            float v21 = Vs[(j0 + 2) * KS_STRIDE + lane + 32];
            float v30 = Vs[(j0 + 3) * KS_STRIDE + lane];
            float v31 = Vs[(j0 + 3) * KS_STRIDE + lane + 32];
#pragma unroll
            for (int rr = 0; rr < 8; rr++) {
                float4 p4 = *(const float4*)(psw + rr * 64 + j0);
                acc0[rr] += p4.x * v00 + p4.y * v10 + p4.z * v20 + p4.w * v30;
                acc1[rr] += p4.x * v01 + p4.y * v11 + p4.z * v21 + p4.w * v31;
            }
        }
        __syncwarp();
    }

    // ---- epilogue: normalize and store [b, q, h, d] ----
#pragma unroll
    for (int rr = 0; rr < 8; rr++) {
        int row = warp * 8 + rr;
        float inv = 1.0f / lsum[rr];
        size_t o = (((size_t)(b * SEQ + q0 + row) * NH + h) << 6);
        g_o[o + lane] = acc0[rr] * inv;
        g_o[o + lane + 32] = acc1[rr] * inv;
    }
}

// ---------------- launch ---------------------------------------------------
extern "C" void kernel_launch(void* const* d_in, const int* in_sizes, int n_in,
                              void* d_out, int out_size)
{
    const float* x    = (const float*)d_in[0];
    const float* cosp = (const float*)d_in[1];
    const float* sinp = (const float*)d_in[2];
    const float* Wq   = (const float*)d_in[3];
    const float* Wk   = (const float*)d_in[4];
    const float* Wv   = (const float*)d_in[5];
    const float* Wo   = (const float*)d_in[6];
    float* out = (float*)d_out;

    float *q, *k, *v, *o;
    cudaGetSymbolAddress((void**)&q, g_q);
    cudaGetSymbolAddress((void**)&k, g_k);
    cudaGetSymbolAddress((void**)&v, g_v);
    cudaGetSymbolAddress((void**)&o, g_o);

    cudaFuncSetAttribute(attn_kernel,
                         cudaFuncAttributeMaxDynamicSharedMemorySize, ATTN_SMEM);

    // Projections
    sgemm_kernel<<<dim3(D_MODEL / BN, TOK / BM), 256>>>(x, Wq, q, TOK, D_MODEL, D_MODEL);
    sgemm_kernel<<<dim3((NKV * HD) / BN, TOK / BM), 256>>>(x, Wk, k, TOK, NKV * HD, D_MODEL);
    sgemm_kernel<<<dim3((NKV * HD) / BN, TOK / BM), 256>>>(x, Wv, v, TOK, NKV * HD, D_MODEL);

    // RoPE + RMSNorm (warp per (token, head)); 8 warps per 256-thread block
    rope_rms_kernel<<<(TOK * NH) / 8, 256>>>(q, cosp, sinp, NH);
    rope_rms_kernel<<<(TOK * NKV) / 8, 256>>>(k, cosp, sinp, NKV);

    // Attention
    attn_kernel<<<dim3(SEQ / 64, NH, BATCH), 256, ATTN_SMEM>>>();

    // Output projection
    sgemm_kernel<<<dim3(D_MODEL / BN, TOK / BM), 256>>>(o, Wo, out, TOK, D_MODEL, D_MODEL);
}

// round 4
// speedup vs baseline: 1.1267x; 1.1267x over previous
#include <cuda_runtime.h>
#include <math.h>
#include <stdint.h>

#define D_MODEL 2048
#define NH 32
#define NKV 8
#define HD 64
#define BATCH 2
#define SEQ 2048
#define TOK (BATCH * SEQ)   // 4096

// ---------------- scratch (device globals; no allocation allowed) ----------
__device__ float g_q[(size_t)TOK * NH * HD];
__device__ float g_k[(size_t)TOK * NKV * HD];
__device__ float g_v[(size_t)TOK * NKV * HD];
__device__ float g_o[(size_t)TOK * NH * HD];
__device__ float g_wqt[(size_t)D_MODEL * D_MODEL];       // Wq^T [N,K]
__device__ float g_wkt[(size_t)(NKV * HD) * D_MODEL];
__device__ float g_wvt[(size_t)(NKV * HD) * D_MODEL];
__device__ float g_wot[(size_t)D_MODEL * D_MODEL];

// ======================= helpers (portable PTX only) ========================
__device__ __forceinline__ uint32_t smem_u32(const void* p) {
    uint32_t a;
    asm("{ .reg .u64 t; cvta.to.shared.u64 t, %1; cvt.u32.u64 %0, t; }"
        : "=r"(a) : "l"(p));
    return a;
}
__device__ __forceinline__ uint32_t f2tf32(float x) {
    uint32_t r;
    asm("cvt.rna.tf32.f32 %0, %1;" : "=r"(r) : "f"(x));
    return r;
}
#define SWZ(o) ((o) ^ (((o) >> 3) & 0x70))

#define LDSM4(r, a) \
    asm volatile("ldmatrix.sync.aligned.m8n8.x4.shared.b16 {%0,%1,%2,%3}, [%4];" \
        : "=r"((r)[0]), "=r"((r)[1]), "=r"((r)[2]), "=r"((r)[3]) : "r"(a))

// operands passed individually so we can permute the A fragment:
// mma wants a0=(r,c), a1=(r+8,c), a2=(r,c+4), a3=(r+8,c+4); our ldmatrix tile
// order yields {(r,c),(r,c+4),(r+8,c),(r+8,c+4)} -> pass {0,2,1,3}.
#define MMA_TF32(c, a0, a1, a2, a3, b0, b1) \
    asm volatile("mma.sync.aligned.m16n8k8.row.col.f32.tf32.tf32.f32 " \
        "{%0,%1,%2,%3}, {%4,%5,%6,%7}, {%8,%9}, {%0,%1,%2,%3};" \
        : "+f"((c)[0]), "+f"((c)[1]), "+f"((c)[2]), "+f"((c)[3]) \
        : "r"(a0), "r"(a1), "r"(a2), "r"(a3), "r"(b0), "r"(b1))

// ======================= 3xTF32 GEMM via mma.sync ===========================
// C[M,N] = A[M,K] @ Wt^T where Wt is [N,K] K-major.
// CTA tile 128x128, BK=32, 8 warps (warp tile 32x64), double-buffered smem.
#define GBM 128
#define GBN 128
#define GBK 32
#define ASZ (GBM * GBK * 4)            // 16 KB
#define BSZ (GBN * GBK * 4)            // 16 KB
#define OFF_AHI 0
#define OFF_ALO (ASZ)
#define OFF_BHI (2 * ASZ)
#define OFF_BLO (2 * ASZ + BSZ)
#define BUFSZ (2 * ASZ + 2 * BSZ)      // 64 KB
#define GEMM_SMEM (2 * BUFSZ)          // 128 KB

__device__ __forceinline__ void sts_split(float4 v, uint32_t hi_a, uint32_t lo_a) {
    uint32_t hx = f2tf32(v.x), hy = f2tf32(v.y), hz = f2tf32(v.z), hw = f2tf32(v.w);
    uint32_t lx = f2tf32(v.x - __uint_as_float(hx));
    uint32_t ly = f2tf32(v.y - __uint_as_float(hy));
    uint32_t lz = f2tf32(v.z - __uint_as_float(hz));
    uint32_t lw = f2tf32(v.w - __uint_as_float(hw));
    asm volatile("st.shared.v4.b32 [%0], {%1,%2,%3,%4};"
                 :: "r"(hi_a), "r"(hx), "r"(hy), "r"(hz), "r"(hw) : "memory");
    asm volatile("st.shared.v4.b32 [%0], {%1,%2,%3,%4};"
                 :: "r"(lo_a), "r"(lx), "r"(ly), "r"(lz), "r"(lw) : "memory");
}

__global__ __launch_bounds__(256, 1)
void gemm_mma_kernel(const float* __restrict__ A, const float* __restrict__ Bt,
                     float* __restrict__ C, int M, int N, int K)
{
    extern __shared__ char sm[];
    const uint32_t sb = smem_u32(sm);
    const int tid = threadIdx.x;
    const int wid = tid >> 5, lane = tid & 31;
    const int m0 = blockIdx.y * GBM;
    const int n0 = blockIdx.x * GBN;
    const int wm = wid & 3;            // 4 warps along M
    const int wn = wid >> 2;           // 2 warps along N

    // gmem load slots: 128 rows x 32 cols fp32, 4 float4 per thread
    const float* apt[4];
    const float* bpt[4];
    uint32_t asw[4];
#pragma unroll
    for (int i = 0; i < 4; i++) {
        int idx = tid + i * 256, r = idx >> 3, c = idx & 7;
        apt[i] = A + (size_t)(m0 + r) * K + c * 4;
        bpt[i] = Bt + (size_t)(n0 + r) * K + c * 4;
        asw[i] = SWZ((uint32_t)(r * 128 + c * 16));
    }

    // ldmatrix per-lane geometry (x4: lanes 0-7 tile0, 8-15 t1, 16-23 t2, 24-31 t3)
    // tile order: t0=(rows0-7,chunkA) t1=(rows0-7,chunkB) t2=(rows8-15,chunkA) t3=(rows8-15,chunkB)
    const int lrow = (lane & 7) + ((lane >> 4) << 3);
    const int lc16 = (lane >> 3) & 1;
    uint32_t a_rb[2]; int a_rx[2];
#pragma unroll
    for (int mi = 0; mi < 2; mi++) {
        int r = wm * 32 + mi * 16 + lrow;
        a_rb[mi] = (uint32_t)(r * 128); a_rx[mi] = r & 7;
    }
    uint32_t b_rb[4]; int b_rx[4];
#pragma unroll
    for (int bi = 0; bi < 4; bi++) {
        int r = wn * 64 + bi * 16 + lrow;
        b_rb[bi] = (uint32_t)(r * 128); b_rx[bi] = r & 7;
    }

    float acc[2][8][4];
#pragma unroll
    for (int mi = 0; mi < 2; mi++)
#pragma unroll
        for (int ni = 0; ni < 8; ni++)
#pragma unroll
            for (int j = 0; j < 4; j++) acc[mi][ni][j] = 0.0f;

    // prologue: load + store stage 0
    float4 a4[4], b4[4];
#pragma unroll
    for (int i = 0; i < 4; i++) { a4[i] = *(const float4*)apt[i]; b4[i] = *(const float4*)bpt[i]; }
    {
        const uint32_t base = sb;
#pragma unroll
        for (int i = 0; i < 4; i++) {
            sts_split(a4[i], base + OFF_AHI + asw[i], base + OFF_ALO + asw[i]);
            sts_split(b4[i], base + OFF_BHI + asw[i], base + OFF_BLO + asw[i]);
        }
    }
    __syncthreads();

    const int S = K / GBK;
    for (int s = 0; s < S; s++) {
        const int buf = s & 1;
        const uint32_t base = sb + buf * BUFSZ;

        if (s + 1 < S) {
            const int k0 = (s + 1) * GBK;
#pragma unroll
            for (int i = 0; i < 4; i++) {
                a4[i] = *(const float4*)(apt[i] + k0);
                b4[i] = *(const float4*)(bpt[i] + k0);
            }
        }

#pragma unroll
        for (int kstep = 0; kstep < 4; kstep++) {
            uint32_t ah[2][4], al[2][4], bh[4][4], bl[4][4];
#pragma unroll
            for (int mi = 0; mi < 2; mi++) {
                uint32_t off = a_rb[mi] + (uint32_t)(((kstep * 2 + lc16) ^ a_rx[mi]) * 16);
                LDSM4(ah[mi], base + OFF_AHI + off);
                LDSM4(al[mi], base + OFF_ALO + off);
            }
#pragma unroll
            for (int bi = 0; bi < 4; bi++) {
                uint32_t off = b_rb[bi] + (uint32_t)(((kstep * 2 + lc16) ^ b_rx[bi]) * 16);
                LDSM4(bh[bi], base + OFF_BHI + off);
                LDSM4(bl[bi], base + OFF_BLO + off);
            }
#pragma unroll
            for (int mi = 0; mi < 2; mi++)
#pragma unroll
                for (int ni = 0; ni < 8; ni++) {
                    uint32_t* bph = &bh[ni >> 1][(ni & 1) * 2];
                    uint32_t* bpl = &bl[ni >> 1][(ni & 1) * 2];
                    // A fragment permuted {0,2,1,3} (see macro comment)
                    MMA_TF32(acc[mi][ni], ah[mi][0], ah[mi][2], ah[mi][1], ah[mi][3],
                             bph[0], bph[1]);
                    MMA_TF32(acc[mi][ni], ah[mi][0], ah[mi][2], ah[mi][1], ah[mi][3],
                             bpl[0], bpl[1]);
                    MMA_TF32(acc[mi][ni], al[mi][0], al[mi][2], al[mi][1], al[mi][3],
                             bph[0], bph[1]);
                }
        }
        __syncthreads();

        if (s + 1 < S) {
            const uint32_t nb = sb + (buf ^ 1) * BUFSZ;
#pragma unroll
            for (int i = 0; i < 4; i++) {
                sts_split(a4[i], nb + OFF_AHI + asw[i], nb + OFF_ALO + asw[i]);
                sts_split(b4[i], nb + OFF_BHI + asw[i], nb + OFF_BLO + asw[i]);
            }
            __syncthreads();
        }
    }

    // epilogue: C fragment -> gmem
#pragma unroll
    for (int mi = 0; mi < 2; mi++)
#pragma unroll
        for (int ni = 0; ni < 8; ni++) {
            int row = m0 + wm * 32 + mi * 16 + (lane >> 2);
            int col = n0 + wn * 64 + ni * 8 + (lane & 3) * 2;
            *(float2*)(C + (size_t)row * N + col) =
                make_float2(acc[mi][ni][0], acc[mi][ni][1]);
            *(float2*)(C + (size_t)(row + 8) * N + col) =
                make_float2(acc[mi][ni][2], acc[mi][ni][3]);
        }
}

// ---------------- transpose: out[C,R] = in[R,C]^T ---------------------------
__global__ void transpose_kernel(const float* __restrict__ in, float* __restrict__ out,
                                 int R, int C)
{
    __shared__ float t[32][33];
    const int bx = blockIdx.x * 32, by = blockIdx.y * 32;
    const int tx = threadIdx.x, ty = threadIdx.y;
#pragma unroll
    for (int j = 0; j < 32; j += 8)
        t[ty + j][tx] = in[(size_t)(by + ty + j) * C + bx + tx];
    __syncthreads();
#pragma unroll
    for (int j = 0; j < 32; j += 8)
        out[(size_t)(bx + ty + j) * R + by + tx] = t[tx][ty + j];
}

// ---------------- RoPE + per-head RMSNorm (one warp per (token, head)) ----
__global__ void rope_rms_kernel(float* __restrict__ buf,
                                const float* __restrict__ cosp,
                                const float* __restrict__ sinp,
                                int nheads)
{
    int gw = (blockIdx.x * blockDim.x + threadIdx.x) >> 5;
    int lane = threadIdx.x & 31;
    int total = TOK * nheads;
    if (gw >= total) return;
    int tok = gw / nheads;
    int l = tok % SEQ;

    float* p = buf + (size_t)gw * HD;
    float x1 = p[lane];
    float x2 = p[lane + 32];
    float c = cosp[l * 32 + lane];
    float s = sinp[l * 32 + lane];
    float o1 = x1 * c - x2 * s;
    float o2 = x2 * c + x1 * s;
    float ss = o1 * o1 + o2 * o2;
#pragma unroll
    for (int off = 16; off > 0; off >>= 1)
        ss += __shfl_xor_sync(0xffffffffu, ss, off);
    float r = rsqrtf(ss * (1.0f / 64.0f) + 1e-6f);
    p[lane] = o1 * r;
    p[lane + 32] = o2 * r;
}

// ---------------- Flash attention, fp32, causal, GQA ----------------------
#define KS_STRIDE 68
#define ATTN_QS   (64 * 64)
#define ATTN_KS   (64 * KS_STRIDE)
#define ATTN_PS   (8 * 8 * 64)
#define ATTN_SMEM ((ATTN_QS + 2 * ATTN_KS + ATTN_PS) * 4)

__global__ __launch_bounds__(256) void attn_kernel()
{
    extern __shared__ float smf[];
    float* Qs = smf;
    float* Ks = Qs + ATTN_QS;
    float* Vs = Ks + ATTN_KS;
    float* ps = Vs + ATTN_KS;

    const int qt = blockIdx.x;
    const int h = blockIdx.y;
    const int b = blockIdx.z;
    const int kvh = h >> 2;
    const int tid = threadIdx.x;
    const int warp = tid >> 5;
    const int lane = tid & 31;
    const int q0 = qt * 64;

#pragma unroll
    for (int it = 0; it < 4; it++) {
        int i = tid + it * 256;
        int r = i >> 4, d4 = (i & 15) << 2;
        const float* qp = g_q + (((size_t)(b * SEQ + q0 + r) * NH + h) << 6) + d4;
        *(float4*)(Qs + r * 64 + d4) = *(const float4*)qp;
    }

    float m[8], lsum[8], acc0[8], acc1[8];
#pragma unroll
    for (int r = 0; r < 8; r++) {
        m[r] = -1e30f; lsum[r] = 0.0f; acc0[r] = 0.0f; acc1[r] = 0.0f;
    }
    const float scale = 0.125f;
    float* psw = ps + warp * (8 * 64);

    for (int kt = 0; kt <= qt; kt++) {
        __syncthreads();
        const int k0 = kt * 64;
#pragma unroll
        for (int it = 0; it < 4; it++) {
            int i = tid + it * 256;
            int r = i >> 4, d4 = (i & 15) << 2;
            size_t gi = (((size_t)(b * SEQ + k0 + r) * NKV + kvh) << 6) + d4;
            float4 k4 = *(const float4*)(g_k + gi);
            float4 v4 = *(const float4*)(g_v + gi);
            *(float4*)(Ks + r * KS_STRIDE + d4) = k4;
            *(float4*)(Vs + r * KS_STRIDE + d4) = v4;
        }
        __syncthreads();

        float s0[8], s1[8];
#pragma unroll
        for (int r = 0; r < 8; r++) { s0[r] = 0.0f; s1[r] = 0.0f; }

        const float* ka_base = Ks + lane * KS_STRIDE;
        const float* kb_base = Ks + (lane + 32) * KS_STRIDE;
#pragma unroll
        for (int d0 = 0; d0 < 64; d0 += 8) {
            float4 ka0 = *(const float4*)(ka_base + d0);
            float4 ka1 = *(const float4*)(ka_base + d0 + 4);
            float4 kb0 = *(const float4*)(kb_base + d0);
            float4 kb1 = *(const float4*)(kb_base + d0 + 4);
#pragma unroll
            for (int rr = 0; rr < 8; rr++) {
                const float* qp = Qs + (warp * 8 + rr) * 64 + d0;
                float4 qa = *(const float4*)qp;
                float4 qb = *(const float4*)(qp + 4);
                s0[rr] += qa.x * ka0.x + qa.y * ka0.y + qa.z * ka0.z + qa.w * ka0.w
                        + qb.x * ka1.x + qb.y * ka1.y + qb.z * ka1.z + qb.w * ka1.w;
                s1[rr] += qa.x * kb0.x + qa.y * kb0.y + qa.z * kb0.z + qa.w * kb0.w
                        + qb.x * kb1.x + qb.y * kb1.y + qb.z * kb1.z + qb.w * kb1.w;
            }
        }

        const bool diag = (kt == qt);
#pragma unroll
        for (int rr = 0; rr < 8; rr++) {
            int qi = q0 + warp * 8 + rr;
            float v0 = s0[rr] * scale;
            float v1 = s1[rr] * scale;
            if (diag) {
                if (k0 + lane > qi) v0 = -1e30f;
                if (k0 + lane + 32 > qi) v1 = -1e30f;
            }
            float mx = fmaxf(v0, v1);
#pragma unroll
            for (int off = 16; off > 0; off >>= 1)
                mx = fmaxf(mx, __shfl_xor_sync(0xffffffffu, mx, off));
            float mnew = fmaxf(m[rr], mx);
            float p0 = __expf(v0 - mnew);
            float p1 = __expf(v1 - mnew);
            float corr = __expf(m[rr] - mnew);
            m[rr] = mnew;
            float pr = p0 + p1;
#pragma unroll
            for (int off = 16; off > 0; off >>= 1)
                pr += __shfl_xor_sync(0xffffffffu, pr, off);
            lsum[rr] = lsum[rr] * corr + pr;
            acc0[rr] *= corr;
            acc1[rr] *= corr;
            psw[rr * 64 + lane] = p0;
            psw[rr * 64 + lane + 32] = p1;
        }
        __syncwarp();

#pragma unroll
        for (int j0 = 0; j0 < 64; j0 += 4) {
            float v00 = Vs[(j0 + 0) * KS_STRIDE + lane];
            float v01 = Vs[(j0 + 0) * KS_STRIDE + lane + 32];
            float v10 = Vs[(j0 + 1) * KS_STRIDE + lane];
            float v11 = Vs[(j0 + 1) * KS_STRIDE + lane + 32];
            float v20 = Vs[(j0 + 2) * KS_STRIDE + lane];
            float v21 = Vs[(j0 + 2) * KS_STRIDE + lane + 32];
            float v30 = Vs[(j0 + 3) * KS_STRIDE + lane];
            float v31 = Vs[(j0 + 3) * KS_STRIDE + lane + 32];
#pragma unroll
            for (int rr = 0; rr < 8; rr++) {
                float4 p4 = *(const float4*)(psw + rr * 64 + j0);
                acc0[rr] += p4.x * v00 + p4.y * v10 + p4.z * v20 + p4.w * v30;
                acc1[rr] += p4.x * v01 + p4.y * v11 + p4.z * v21 + p4.w * v31;
            }
        }
        __syncwarp();
    }

#pragma unroll
    for (int rr = 0; rr < 8; rr++) {
        int row = warp * 8 + rr;
        float inv = 1.0f / lsum[rr];
        size_t o = (((size_t)(b * SEQ + q0 + row) * NH + h) << 6);
        g_o[o + lane] = acc0[rr] * inv;
        g_o[o + lane + 32] = acc1[rr] * inv;
    }
}

// ---------------- launch ---------------------------------------------------
extern "C" void kernel_launch(void* const* d_in, const int* in_sizes, int n_in,
                              void* d_out, int out_size)
{
    const float* x    = (const float*)d_in[0];
    const float* cosp = (const float*)d_in[1];
    const float* sinp = (const float*)d_in[2];
    const float* Wq   = (const float*)d_in[3];
    const float* Wk   = (const float*)d_in[4];
    const float* Wv   = (const float*)d_in[5];
    const float* Wo   = (const float*)d_in[6];
    float* out = (float*)d_out;

    float *q, *k, *v, *o, *wqt, *wkt, *wvt, *wot;
    cudaGetSymbolAddress((void**)&q, g_q);
    cudaGetSymbolAddress((void**)&k, g_k);
    cudaGetSymbolAddress((void**)&v, g_v);
    cudaGetSymbolAddress((void**)&o, g_o);
    cudaGetSymbolAddress((void**)&wqt, g_wqt);
    cudaGetSymbolAddress((void**)&wkt, g_wkt);
    cudaGetSymbolAddress((void**)&wvt, g_wvt);
    cudaGetSymbolAddress((void**)&wot, g_wot);

    cudaFuncSetAttribute(gemm_mma_kernel,
                         cudaFuncAttributeMaxDynamicSharedMemorySize, GEMM_SMEM);
    cudaFuncSetAttribute(attn_kernel,
                         cudaFuncAttributeMaxDynamicSharedMemorySize, ATTN_SMEM);

    // transpose weights -> [N, K] K-major
    dim3 tb(32, 8);
    transpose_kernel<<<dim3(D_MODEL / 32, D_MODEL / 32), tb>>>(Wq, wqt, D_MODEL, D_MODEL);
    transpose_kernel<<<dim3((NKV * HD) / 32, D_MODEL / 32), tb>>>(Wk, wkt, D_MODEL, NKV * HD);
    transpose_kernel<<<dim3((NKV * HD) / 32, D_MODEL / 32), tb>>>(Wv, wvt, D_MODEL, NKV * HD);
    transpose_kernel<<<dim3(D_MODEL / 32, D_MODEL / 32), tb>>>(Wo, wot, D_MODEL, D_MODEL);

    // projections (mma.sync tf32, 3x split)
    gemm_mma_kernel<<<dim3(D_MODEL / GBN, TOK / GBM), 256, GEMM_SMEM>>>(
        x, wqt, q, TOK, D_MODEL, D_MODEL);
    gemm_mma_kernel<<<dim3((NKV * HD) / GBN, TOK / GBM), 256, GEMM_SMEM>>>(
        x, wkt, k, TOK, NKV * HD, D_MODEL);
    gemm_mma_kernel<<<dim3((NKV * HD) / GBN, TOK / GBM), 256, GEMM_SMEM>>>(
        x, wvt, v, TOK, NKV * HD, D_MODEL);

    rope_rms_kernel<<<(TOK * NH) / 8, 256>>>(q, cosp, sinp, NH);
    rope_rms_kernel<<<(TOK * NKV) / 8, 256>>>(k, cosp, sinp, NKV);

    attn_kernel<<<dim3(SEQ / 64, NH, BATCH), 256, ATTN_SMEM>>>();

    gemm_mma_kernel<<<dim3(D_MODEL / GBN, TOK / GBM), 256, GEMM_SMEM>>>(
        o, wot, out, TOK, D_MODEL, D_MODEL);
}

// round 5
// speedup vs baseline: 1.2444x; 1.1044x over previous
#include <cuda_runtime.h>
#include <math.h>
#include <stdint.h>

#define D_MODEL 2048
#define NH 32
#define NKV 8
#define HD 64
#define BATCH 2
#define SEQ 2048
#define TOK (BATCH * SEQ)   // 4096

// ---------------- scratch (device globals; no allocation allowed) ----------
__device__ float g_q[(size_t)TOK * NH * HD];
__device__ float g_k[(size_t)TOK * NKV * HD];
__device__ float g_v[(size_t)TOK * NKV * HD];
__device__ float g_o[(size_t)TOK * NH * HD];
__device__ float g_wqt[(size_t)D_MODEL * D_MODEL];       // Wq^T [N,K]
__device__ float g_wkt[(size_t)(NKV * HD) * D_MODEL];
__device__ float g_wvt[(size_t)(NKV * HD) * D_MODEL];
__device__ float g_wot[(size_t)D_MODEL * D_MODEL];

// ======================= helpers (portable PTX only) ========================
__device__ __forceinline__ uint32_t smem_u32(const void* p) {
    uint32_t a;
    asm("{ .reg .u64 t; cvta.to.shared.u64 t, %1; cvt.u32.u64 %0, t; }"
        : "=r"(a) : "l"(p));
    return a;
}
__device__ __forceinline__ uint32_t f2tf32(float x) {
    uint32_t r;
    asm("cvt.rna.tf32.f32 %0, %1;" : "=r"(r) : "f"(x));
    return r;
}
#define SWZ(o) ((o) ^ (((o) >> 3) & 0x70))

#define LDSM4(r, a) \
    asm volatile("ldmatrix.sync.aligned.m8n8.x4.shared.b16 {%0,%1,%2,%3}, [%4];" \
        : "=r"((r)[0]), "=r"((r)[1]), "=r"((r)[2]), "=r"((r)[3]) : "r"(a))

// mma wants a0=(r,c), a1=(r+8,c), a2=(r,c+4), a3=(r+8,c+4); our ldmatrix tile
// order yields {(r,c),(r,c+4),(r+8,c),(r+8,c+4)} -> pass {0,2,1,3}.
#define MMA_TF32(c, a0, a1, a2, a3, b0, b1) \
    asm volatile("mma.sync.aligned.m16n8k8.row.col.f32.tf32.tf32.f32 " \
        "{%0,%1,%2,%3}, {%4,%5,%6,%7}, {%8,%9}, {%0,%1,%2,%3};" \
        : "+f"((c)[0]), "+f"((c)[1]), "+f"((c)[2]), "+f"((c)[3]) \
        : "r"(a0), "r"(a1), "r"(a2), "r"(a3), "r"(b0), "r"(b1))

__device__ __forceinline__ void sts_split(float4 v, uint32_t hi_a, uint32_t lo_a) {
    uint32_t hx = f2tf32(v.x), hy = f2tf32(v.y), hz = f2tf32(v.z), hw = f2tf32(v.w);
    uint32_t lx = f2tf32(v.x - __uint_as_float(hx));
    uint32_t ly = f2tf32(v.y - __uint_as_float(hy));
    uint32_t lz = f2tf32(v.z - __uint_as_float(hz));
    uint32_t lw = f2tf32(v.w - __uint_as_float(hw));
    asm volatile("st.shared.v4.b32 [%0], {%1,%2,%3,%4};"
                 :: "r"(hi_a), "r"(hx), "r"(hy), "r"(hz), "r"(hw) : "memory");
    asm volatile("st.shared.v4.b32 [%0], {%1,%2,%3,%4};"
                 :: "r"(lo_a), "r"(lx), "r"(ly), "r"(lz), "r"(lw) : "memory");
}

// ======================= 3xTF32 GEMM via mma.sync (R4, unchanged) ==========
#define GBM 128
#define GBN 128
#define GBK 32
#define ASZ (GBM * GBK * 4)
#define BSZ (GBN * GBK * 4)
#define OFF_AHI 0
#define OFF_ALO (ASZ)
#define OFF_BHI (2 * ASZ)
#define OFF_BLO (2 * ASZ + BSZ)
#define BUFSZ (2 * ASZ + 2 * BSZ)
#define GEMM_SMEM (2 * BUFSZ)

__global__ __launch_bounds__(256, 1)
void gemm_mma_kernel(const float* __restrict__ A, const float* __restrict__ Bt,
                     float* __restrict__ C, int M, int N, int K)
{
    extern __shared__ char sm[];
    const uint32_t sb = smem_u32(sm);
    const int tid = threadIdx.x;
    const int wid = tid >> 5, lane = tid & 31;
    const int m0 = blockIdx.y * GBM;
    const int n0 = blockIdx.x * GBN;
    const int wm = wid & 3;
    const int wn = wid >> 2;

    const float* apt[4];
    const float* bpt[4];
    uint32_t asw[4];
#pragma unroll
    for (int i = 0; i < 4; i++) {
        int idx = tid + i * 256, r = idx >> 3, c = idx & 7;
        apt[i] = A + (size_t)(m0 + r) * K + c * 4;
        bpt[i] = Bt + (size_t)(n0 + r) * K + c * 4;
        asw[i] = SWZ((uint32_t)(r * 128 + c * 16));
    }

    const int lrow = (lane & 7) + ((lane >> 4) << 3);
    const int lc16 = (lane >> 3) & 1;
    uint32_t a_rb[2]; int a_rx[2];
#pragma unroll
    for (int mi = 0; mi < 2; mi++) {
        int r = wm * 32 + mi * 16 + lrow;
        a_rb[mi] = (uint32_t)(r * 128); a_rx[mi] = r & 7;
    }
    uint32_t b_rb[4]; int b_rx[4];
#pragma unroll
    for (int bi = 0; bi < 4; bi++) {
        int r = wn * 64 + bi * 16 + lrow;
        b_rb[bi] = (uint32_t)(r * 128); b_rx[bi] = r & 7;
    }

    float acc[2][8][4];
#pragma unroll
    for (int mi = 0; mi < 2; mi++)
#pragma unroll
        for (int ni = 0; ni < 8; ni++)
#pragma unroll
            for (int j = 0; j < 4; j++) acc[mi][ni][j] = 0.0f;

    float4 a4[4], b4[4];
#pragma unroll
    for (int i = 0; i < 4; i++) { a4[i] = *(const float4*)apt[i]; b4[i] = *(const float4*)bpt[i]; }
    {
        const uint32_t base = sb;
#pragma unroll
        for (int i = 0; i < 4; i++) {
            sts_split(a4[i], base + OFF_AHI + asw[i], base + OFF_ALO + asw[i]);
            sts_split(b4[i], base + OFF_BHI + asw[i], base + OFF_BLO + asw[i]);
        }
    }
    __syncthreads();

    const int S = K / GBK;
    for (int s = 0; s < S; s++) {
        const int buf = s & 1;
        const uint32_t base = sb + buf * BUFSZ;

        if (s + 1 < S) {
            const int k0 = (s + 1) * GBK;
#pragma unroll
            for (int i = 0; i < 4; i++) {
                a4[i] = *(const float4*)(apt[i] + k0);
                b4[i] = *(const float4*)(bpt[i] + k0);
            }
        }

#pragma unroll
        for (int kstep = 0; kstep < 4; kstep++) {
            uint32_t ah[2][4], al[2][4], bh[4][4], bl[4][4];
#pragma unroll
            for (int mi = 0; mi < 2; mi++) {
                uint32_t off = a_rb[mi] + (uint32_t)(((kstep * 2 + lc16) ^ a_rx[mi]) * 16);
                LDSM4(ah[mi], base + OFF_AHI + off);
                LDSM4(al[mi], base + OFF_ALO + off);
            }
#pragma unroll
            for (int bi = 0; bi < 4; bi++) {
                uint32_t off = b_rb[bi] + (uint32_t)(((kstep * 2 + lc16) ^ b_rx[bi]) * 16);
                LDSM4(bh[bi], base + OFF_BHI + off);
                LDSM4(bl[bi], base + OFF_BLO + off);
            }
#pragma unroll
            for (int mi = 0; mi < 2; mi++)
#pragma unroll
                for (int ni = 0; ni < 8; ni++) {
                    uint32_t* bph = &bh[ni >> 1][(ni & 1) * 2];
                    uint32_t* bpl = &bl[ni >> 1][(ni & 1) * 2];
                    MMA_TF32(acc[mi][ni], ah[mi][0], ah[mi][2], ah[mi][1], ah[mi][3],
                             bph[0], bph[1]);
                    MMA_TF32(acc[mi][ni], ah[mi][0], ah[mi][2], ah[mi][1], ah[mi][3],
                             bpl[0], bpl[1]);
                    MMA_TF32(acc[mi][ni], al[mi][0], al[mi][2], al[mi][1], al[mi][3],
                             bph[0], bph[1]);
                }
        }
        __syncthreads();

        if (s + 1 < S) {
            const uint32_t nb = sb + (buf ^ 1) * BUFSZ;
#pragma unroll
            for (int i = 0; i < 4; i++) {
                sts_split(a4[i], nb + OFF_AHI + asw[i], nb + OFF_ALO + asw[i]);
                sts_split(b4[i], nb + OFF_BHI + asw[i], nb + OFF_BLO + asw[i]);
            }
            __syncthreads();
        }
    }

#pragma unroll
    for (int mi = 0; mi < 2; mi++)
#pragma unroll
        for (int ni = 0; ni < 8; ni++) {
            int row = m0 + wm * 32 + mi * 16 + (lane >> 2);
            int col = n0 + wn * 64 + ni * 8 + (lane & 3) * 2;
            *(float2*)(C + (size_t)row * N + col) =
                make_float2(acc[mi][ni][0], acc[mi][ni][1]);
            *(float2*)(C + (size_t)(row + 8) * N + col) =
                make_float2(acc[mi][ni][2], acc[mi][ni][3]);
        }
}

// ---------------- transpose: out[C,R] = in[R,C]^T ---------------------------
__global__ void transpose_kernel(const float* __restrict__ in, float* __restrict__ out,
                                 int R, int C)
{
    __shared__ float t[32][33];
    const int bx = blockIdx.x * 32, by = blockIdx.y * 32;
    const int tx = threadIdx.x, ty = threadIdx.y;
#pragma unroll
    for (int j = 0; j < 32; j += 8)
        t[ty + j][tx] = in[(size_t)(by + ty + j) * C + bx + tx];
    __syncthreads();
#pragma unroll
    for (int j = 0; j < 32; j += 8)
        out[(size_t)(bx + ty + j) * R + by + tx] = t[tx][ty + j];
}

// ---------------- RoPE + per-head RMSNorm (one warp per (token, head)) ----
__global__ void rope_rms_kernel(float* __restrict__ buf,
                                const float* __restrict__ cosp,
                                const float* __restrict__ sinp,
                                int nheads)
{
    int gw = (blockIdx.x * blockDim.x + threadIdx.x) >> 5;
    int lane = threadIdx.x & 31;
    int total = TOK * nheads;
    if (gw >= total) return;
    int tok = gw / nheads;
    int l = tok % SEQ;

    float* p = buf + (size_t)gw * HD;
    float x1 = p[lane];
    float x2 = p[lane + 32];
    float c = cosp[l * 32 + lane];
    float s = sinp[l * 32 + lane];
    float o1 = x1 * c - x2 * s;
    float o2 = x2 * c + x1 * s;
    float ss = o1 * o1 + o2 * o2;
#pragma unroll
    for (int off = 16; off > 0; off >>= 1)
        ss += __shfl_xor_sync(0xffffffffu, ss, off);
    float r = rsqrtf(ss * (1.0f / 64.0f) + 1e-6f);
    p[lane] = o1 * r;
    p[lane + 32] = o2 * r;
}

// =============== Flash attention via 3xTF32 mma.sync =======================
// CTA: 128 queries, 8 warps, 16 query rows per warp. Key tiles of 64.
// Smem byte offsets (all regions swizzled, 128B logical rows, 32-float chunks):
#define QHI_B 0u
#define QLO_B 32768u
#define KHI_B 65536u
#define KLO_B 81920u
#define VHI_B 98304u
#define VLO_B 114688u
#define PHI_B 131072u
#define PLO_B 163840u
#define ATTN_SMEM 196608

__global__ __launch_bounds__(256, 1) void attn_mma_kernel()
{
    extern __shared__ float smf[];
    const uint32_t sb = smem_u32(smf);
    const int qt = (int)gridDim.x - 1 - (int)blockIdx.x;  // heavy tiles first
    const int h = blockIdx.y, b = blockIdx.z;
    const int kvh = h >> 2;
    const int tid = threadIdx.x;
    const int warp = tid >> 5, lane = tid & 31;
    const int q0 = qt * 128;

    // ---- load Q tile (128x64) -> hi/lo, chunked [2][128][32], swizzled ----
#pragma unroll
    for (int it = 0; it < 8; it++) {
        int idx = tid + it * 256;
        int row = idx >> 4, d4 = (idx & 15) << 2;
        float4 v = *(const float4*)(g_q + (((size_t)(b * SEQ + q0 + row) * NH + h) << 6) + d4);
        uint32_t byte = (uint32_t)(d4 >> 5) * 16384u + SWZ((uint32_t)(row * 128 + (d4 & 31) * 4));
        sts_split(v, sb + QHI_B + byte, sb + QLO_B + byte);
    }

    // fragment geometry
    const int lrow = (lane & 7) + ((lane >> 4) << 3);
    const int lc16 = (lane >> 3) & 1;
    const int ar = warp * 16 + lrow;            // A-frag row (Q and P share it)
    const uint32_t a_rb = (uint32_t)(ar * 128);
    const int a_rx = ar & 7;
    uint32_t b_rb[4]; int b_rx[4];
#pragma unroll
    for (int bi = 0; bi < 4; bi++) {
        int r = bi * 16 + lrow;
        b_rb[bi] = (uint32_t)(r * 128); b_rx[bi] = r & 7;
    }

    float m0 = -1e30f, m1 = -1e30f, l0 = 0.f, l1 = 0.f;
    float oacc[8][4];
#pragma unroll
    for (int nt = 0; nt < 8; nt++)
#pragma unroll
        for (int j = 0; j < 4; j++) oacc[nt][j] = 0.f;

    const int rloc = lane >> 2;                 // C-frag local row (0-7)
    const int qrow0 = q0 + warp * 16 + rloc;    // global query of regs {0,1}
    const int qrow1 = qrow0 + 8;                // global query of regs {2,3}
    const int ktmax = 2 * qt + 1;

    for (int kt = 0; kt <= ktmax; kt++) {
        const int k0 = kt * 64;
        __syncthreads();   // previous tile's K/V consumers done
        // ---- load K (64x64) and V transposed (Vt[dim][key]) ----
#pragma unroll
        for (int it = 0; it < 4; it++) {
            int idx = tid + it * 256;
            int row = idx >> 4, d4 = (idx & 15) << 2;
            size_t gi = (((size_t)(b * SEQ + k0 + row) * NKV + kvh) << 6) + d4;
            float4 kv = *(const float4*)(g_k + gi);
            uint32_t kb = (uint32_t)(d4 >> 5) * 8192u + SWZ((uint32_t)(row * 128 + (d4 & 31) * 4));
            sts_split(kv, sb + KHI_B + kb, sb + KLO_B + kb);
            float4 vv = *(const float4*)(g_v + gi);
            uint32_t vchunk = (uint32_t)(row >> 5) * 8192u;
            int colb = (row & 31) * 4;
            float vals[4] = {vv.x, vv.y, vv.z, vv.w};
#pragma unroll
            for (int j = 0; j < 4; j++) {
                uint32_t vb = vchunk + SWZ((uint32_t)((d4 + j) * 128 + colb));
                uint32_t hi = f2tf32(vals[j]);
                uint32_t lo = f2tf32(vals[j] - __uint_as_float(hi));
                asm volatile("st.shared.b32 [%0], %1;" :: "r"(sb + VHI_B + vb), "r"(hi) : "memory");
                asm volatile("st.shared.b32 [%0], %1;" :: "r"(sb + VLO_B + vb), "r"(lo) : "memory");
            }
        }
        __syncthreads();

        // ---- S = Q @ K^T  (16 rows x 64 keys per warp) ----
        float sacc[8][4];
#pragma unroll
        for (int nt = 0; nt < 8; nt++)
#pragma unroll
            for (int j = 0; j < 4; j++) sacc[nt][j] = 0.f;

#pragma unroll
        for (int ks = 0; ks < 8; ks++) {
            const uint32_t aoff = a_rb + (uint32_t)((((ks & 3) * 2 + lc16) ^ a_rx) * 16);
            const uint32_t qc = (uint32_t)(ks >> 2) * 16384u;
            uint32_t qh[4], ql[4];
            LDSM4(qh, sb + QHI_B + qc + aoff);
            LDSM4(ql, sb + QLO_B + qc + aoff);
            const uint32_t kc = (uint32_t)(ks >> 2) * 8192u;
            uint32_t kh[4][4], kl[4][4];
#pragma unroll
            for (int bi = 0; bi < 4; bi++) {
                uint32_t boff = b_rb[bi] + (uint32_t)((((ks & 3) * 2 + lc16) ^ b_rx[bi]) * 16);
                LDSM4(kh[bi], sb + KHI_B + kc + boff);
                LDSM4(kl[bi], sb + KLO_B + kc + boff);
            }
#pragma unroll
            for (int nt = 0; nt < 8; nt++) {
                uint32_t* bh = &kh[nt >> 1][(nt & 1) * 2];
                uint32_t* bl = &kl[nt >> 1][(nt & 1) * 2];
                MMA_TF32(sacc[nt], qh[0], qh[2], qh[1], qh[3], bh[0], bh[1]);
                MMA_TF32(sacc[nt], qh[0], qh[2], qh[1], qh[3], bl[0], bl[1]);
                MMA_TF32(sacc[nt], ql[0], ql[2], ql[1], ql[3], bh[0], bh[1]);
            }
        }

        // ---- online softmax in C-fragments ----
        const bool domask = (k0 + 63 > q0);
#pragma unroll
        for (int nt = 0; nt < 8; nt++) {
            int keyb = k0 + nt * 8 + (lane & 3) * 2;
#pragma unroll
            for (int j = 0; j < 4; j++) {
                float s = sacc[nt][j] * 0.125f;
                if (domask) {
                    int key = keyb + (j & 1);
                    int qq = (j < 2) ? qrow0 : qrow1;
                    if (key > qq) s = -1e30f;
                }
                sacc[nt][j] = s;
            }
        }
        float mx0 = -1e30f, mx1 = -1e30f;
#pragma unroll
        for (int nt = 0; nt < 8; nt++) {
            mx0 = fmaxf(mx0, fmaxf(sacc[nt][0], sacc[nt][1]));
            mx1 = fmaxf(mx1, fmaxf(sacc[nt][2], sacc[nt][3]));
        }
        mx0 = fmaxf(mx0, __shfl_xor_sync(0xffffffffu, mx0, 1));
        mx0 = fmaxf(mx0, __shfl_xor_sync(0xffffffffu, mx0, 2));
        mx1 = fmaxf(mx1, __shfl_xor_sync(0xffffffffu, mx1, 1));
        mx1 = fmaxf(mx1, __shfl_xor_sync(0xffffffffu, mx1, 2));
        float nm0 = fmaxf(m0, mx0), nm1 = fmaxf(m1, mx1);
        float c0 = __expf(m0 - nm0), c1 = __expf(m1 - nm1);
        m0 = nm0; m1 = nm1;
        float rs0 = 0.f, rs1 = 0.f;
#pragma unroll
        for (int nt = 0; nt < 8; nt++) {
            float p0 = __expf(sacc[nt][0] - nm0);
            float p1 = __expf(sacc[nt][1] - nm0);
            float p2 = __expf(sacc[nt][2] - nm1);
            float p3 = __expf(sacc[nt][3] - nm1);
            sacc[nt][0] = p0; sacc[nt][1] = p1; sacc[nt][2] = p2; sacc[nt][3] = p3;
            rs0 += p0 + p1; rs1 += p2 + p3;
        }
        rs0 += __shfl_xor_sync(0xffffffffu, rs0, 1);
        rs0 += __shfl_xor_sync(0xffffffffu, rs0, 2);
        rs1 += __shfl_xor_sync(0xffffffffu, rs1, 1);
        rs1 += __shfl_xor_sync(0xffffffffu, rs1, 2);
        l0 = l0 * c0 + rs0;
        l1 = l1 * c1 + rs1;
#pragma unroll
        for (int nt = 0; nt < 8; nt++) {
            oacc[nt][0] *= c0; oacc[nt][1] *= c0;
            oacc[nt][2] *= c1; oacc[nt][3] *= c1;
        }

        // ---- store P hi/lo to smem (this warp's 16 rows only) ----
        const int prow0 = warp * 16 + rloc;
#pragma unroll
        for (int nt = 0; nt < 8; nt++) {
            int keyl = nt * 8 + (lane & 3) * 2;
            uint32_t chunk = (uint32_t)(keyl >> 5) * 16384u;
            uint32_t by0 = chunk + SWZ((uint32_t)(prow0 * 128 + (keyl & 31) * 4));
            uint32_t by1 = chunk + SWZ((uint32_t)((prow0 + 8) * 128 + (keyl & 31) * 4));
            uint32_t h0 = f2tf32(sacc[nt][0]), h1 = f2tf32(sacc[nt][1]);
            uint32_t h2 = f2tf32(sacc[nt][2]), h3 = f2tf32(sacc[nt][3]);
            uint32_t lo0 = f2tf32(sacc[nt][0] - __uint_as_float(h0));
            uint32_t lo1 = f2tf32(sacc[nt][1] - __uint_as_float(h1));
            uint32_t lo2 = f2tf32(sacc[nt][2] - __uint_as_float(h2));
            uint32_t lo3 = f2tf32(sacc[nt][3] - __uint_as_float(h3));
            asm volatile("st.shared.v2.b32 [%0], {%1,%2};" :: "r"(sb + PHI_B + by0), "r"(h0), "r"(h1) : "memory");
            asm volatile("st.shared.v2.b32 [%0], {%1,%2};" :: "r"(sb + PLO_B + by0), "r"(lo0), "r"(lo1) : "memory");
            asm volatile("st.shared.v2.b32 [%0], {%1,%2};" :: "r"(sb + PHI_B + by1), "r"(h2), "r"(h3) : "memory");
            asm volatile("st.shared.v2.b32 [%0], {%1,%2};" :: "r"(sb + PLO_B + by1), "r"(lo2), "r"(lo3) : "memory");
        }
        __syncwarp();

        // ---- O += P @ V  (A = P 16xkeys, B = Vt dims x keys) ----
#pragma unroll
        for (int ks = 0; ks < 8; ks++) {
            const uint32_t aoff = a_rb + (uint32_t)((((ks & 3) * 2 + lc16) ^ a_rx) * 16);
            const uint32_t pc = (uint32_t)(ks >> 2) * 16384u;
            uint32_t ph[4], pl[4];
            LDSM4(ph, sb + PHI_B + pc + aoff);
            LDSM4(pl, sb + PLO_B + pc + aoff);
            const uint32_t vc = (uint32_t)(ks >> 2) * 8192u;
            uint32_t vh[4][4], vl[4][4];
#pragma unroll
            for (int bi = 0; bi < 4; bi++) {
                uint32_t boff = b_rb[bi] + (uint32_t)((((ks & 3) * 2 + lc16) ^ b_rx[bi]) * 16);
                LDSM4(vh[bi], sb + VHI_B + vc + boff);
                LDSM4(vl[bi], sb + VLO_B + vc + boff);
            }
#pragma unroll
            for (int nt = 0; nt < 8; nt++) {
                uint32_t* bh = &vh[nt >> 1][(nt & 1) * 2];
                uint32_t* bl = &vl[nt >> 1][(nt & 1) * 2];
                MMA_TF32(oacc[nt], ph[0], ph[2], ph[1], ph[3], bh[0], bh[1]);
                MMA_TF32(oacc[nt], ph[0], ph[2], ph[1], ph[3], bl[0], bl[1]);
                MMA_TF32(oacc[nt], pl[0], pl[2], pl[1], pl[3], bh[0], bh[1]);
            }
        }
    }

    // ---- epilogue: normalize, store [b, q, h, d] ----
    float inv0 = 1.0f / l0, inv1 = 1.0f / l1;
    size_t o0 = (((size_t)(b * SEQ + qrow0) * NH + h) << 6);
    size_t o1 = (((size_t)(b * SEQ + qrow1) * NH + h) << 6);
#pragma unroll
    for (int nt = 0; nt < 8; nt++) {
        int dim = nt * 8 + (lane & 3) * 2;
        *(float2*)(g_o + o0 + dim) = make_float2(oacc[nt][0] * inv0, oacc[nt][1] * inv0);
        *(float2*)(g_o + o1 + dim) = make_float2(oacc[nt][2] * inv1, oacc[nt][3] * inv1);
    }
}

// ---------------- launch ---------------------------------------------------
extern "C" void kernel_launch(void* const* d_in, const int* in_sizes, int n_in,
                              void* d_out, int out_size)
{
    const float* x    = (const float*)d_in[0];
    const float* cosp = (const float*)d_in[1];
    const float* sinp = (const float*)d_in[2];
    const float* Wq   = (const float*)d_in[3];
    const float* Wk   = (const float*)d_in[4];
    const float* Wv   = (const float*)d_in[5];
    const float* Wo   = (const float*)d_in[6];
    float* out = (float*)d_out;

    float *q, *k, *v, *o, *wqt, *wkt, *wvt, *wot;
    cudaGetSymbolAddress((void**)&q, g_q);
    cudaGetSymbolAddress((void**)&k, g_k);
    cudaGetSymbolAddress((void**)&v, g_v);
    cudaGetSymbolAddress((void**)&o, g_o);
    cudaGetSymbolAddress((void**)&wqt, g_wqt);
    cudaGetSymbolAddress((void**)&wkt, g_wkt);
    cudaGetSymbolAddress((void**)&wvt, g_wvt);
    cudaGetSymbolAddress((void**)&wot, g_wot);

    cudaFuncSetAttribute(gemm_mma_kernel,
                         cudaFuncAttributeMaxDynamicSharedMemorySize, GEMM_SMEM);
    cudaFuncSetAttribute(attn_mma_kernel,
                         cudaFuncAttributeMaxDynamicSharedMemorySize, ATTN_SMEM);

    // transpose weights -> [N, K] K-major
    dim3 tb(32, 8);
    transpose_kernel<<<dim3(D_MODEL / 32, D_MODEL / 32), tb>>>(Wq, wqt, D_MODEL, D_MODEL);
    transpose_kernel<<<dim3((NKV * HD) / 32, D_MODEL / 32), tb>>>(Wk, wkt, D_MODEL, NKV * HD);
    transpose_kernel<<<dim3((NKV * HD) / 32, D_MODEL / 32), tb>>>(Wv, wvt, D_MODEL, NKV * HD);
    transpose_kernel<<<dim3(D_MODEL / 32, D_MODEL / 32), tb>>>(Wo, wot, D_MODEL, D_MODEL);

    // projections (mma.sync tf32, 3x split)
    gemm_mma_kernel<<<dim3(D_MODEL / GBN, TOK / GBM), 256, GEMM_SMEM>>>(
        x, wqt, q, TOK, D_MODEL, D_MODEL);
    gemm_mma_kernel<<<dim3((NKV * HD) / GBN, TOK / GBM), 256, GEMM_SMEM>>>(
        x, wkt, k, TOK, NKV * HD, D_MODEL);
    gemm_mma_kernel<<<dim3((NKV * HD) / GBN, TOK / GBM), 256, GEMM_SMEM>>>(
        x, wvt, v, TOK, NKV * HD, D_MODEL);

    rope_rms_kernel<<<(TOK * NH) / 8, 256>>>(q, cosp, sinp, NH);
    rope_rms_kernel<<<(TOK * NKV) / 8, 256>>>(k, cosp, sinp, NKV);

    // attention (mma.sync tf32 flash attention)
    attn_mma_kernel<<<dim3(SEQ / 128, NH, BATCH), 256, ATTN_SMEM>>>();

    gemm_mma_kernel<<<dim3(D_MODEL / GBN, TOK / GBM), 256, GEMM_SMEM>>>(
        o, wot, out, TOK, D_MODEL, D_MODEL);
}

// round 6
// speedup vs baseline: 2.7520x; 2.2115x over previous
#include <cuda_runtime.h>
#include <cuda_fp16.h>
#include <math.h>
#include <stdint.h>

#define D_MODEL 2048
#define NH 32
#define NKV 8
#define HD 64
#define BATCH 2
#define SEQ 2048
#define TOK (BATCH * SEQ)   // 4096

// ---------------- scratch (device globals; no allocation allowed) ----------
__device__ float g_q[(size_t)TOK * NH * HD];
__device__ float g_k[(size_t)TOK * NKV * HD];
__device__ float g_v[(size_t)TOK * NKV * HD];
__device__ float g_o[(size_t)TOK * NH * HD];
__device__ float g_wqt[(size_t)D_MODEL * D_MODEL];       // Wq^T [N,K]
__device__ float g_wkt[(size_t)(NKV * HD) * D_MODEL];
__device__ float g_wvt[(size_t)(NKV * HD) * D_MODEL];
__device__ float g_wot[(size_t)D_MODEL * D_MODEL];

// ======================= helpers (portable PTX only) ========================
__device__ __forceinline__ uint32_t smem_u32(const void* p) {
    uint32_t a;
    asm("{ .reg .u64 t; cvta.to.shared.u64 t, %1; cvt.u32.u64 %0, t; }"
        : "=r"(a) : "l"(p));
    return a;
}
#define SWZ(o)   ((o) ^ (((o) >> 3) & 0x70))   // 128-byte rows
#define SWZ64(o) ((o) ^ (((o) >> 3) & 0x30))   // 64-byte rows

#define LDSM4(r, a) \
    asm volatile("ldmatrix.sync.aligned.m8n8.x4.shared.b16 {%0,%1,%2,%3}, [%4];" \
        : "=r"((r)[0]), "=r"((r)[1]), "=r"((r)[2]), "=r"((r)[3]) : "r"(a))

// fp16 mma, canonical fragments (no permutation needed)
#define MMA_F16(c, a, b0, b1) \
    asm volatile("mma.sync.aligned.m16n8k16.row.col.f32.f16.f16.f32 " \
        "{%0,%1,%2,%3}, {%4,%5,%6,%7}, {%8,%9}, {%0,%1,%2,%3};" \
        : "+f"((c)[0]), "+f"((c)[1]), "+f"((c)[2]), "+f"((c)[3]) \
        : "r"((a)[0]), "r"((a)[1]), "r"((a)[2]), "r"((a)[3]), \
          "r"(b0), "r"(b1))

__device__ __forceinline__ uint32_t packh2(__half a, __half b) {
    __half2 t = __halves2half2(a, b);
    return *(uint32_t*)&t;
}
__device__ __forceinline__ void split_pair(float f0, float f1,
                                           uint32_t& hp, uint32_t& lp) {
    __half h0 = __float2half_rn(f0), h1 = __float2half_rn(f1);
    __half l0 = __float2half_rn(f0 - __half2float(h0));
    __half l1 = __float2half_rn(f1 - __half2float(h1));
    hp = packh2(h0, h1); lp = packh2(l0, l1);
}
// store float4 as 2 planes of half2 pairs (8 bytes each)
__device__ __forceinline__ void sts_split_h(float4 v, uint32_t hi_a, uint32_t lo_a) {
    uint32_t h01, l01, h23, l23;
    split_pair(v.x, v.y, h01, l01);
    split_pair(v.z, v.w, h23, l23);
    asm volatile("st.shared.v2.b32 [%0], {%1,%2};" :: "r"(hi_a), "r"(h01), "r"(h23) : "memory");
    asm volatile("st.shared.v2.b32 [%0], {%1,%2};" :: "r"(lo_a), "r"(l01), "r"(l23) : "memory");
}

// ======================= 3xFP16 GEMM via mma.sync ===========================
// C[M,N] = A[M,K] @ Wt^T, Wt [N,K] K-major. CTA 128x128, BK=32, 8 warps.
// fp16 planes: 64-byte rows (32 halves), SW64 swizzle.
#define GBM 128
#define GBN 128
#define GBK 32
#define APL 8192                       // 128*32*2
#define OFF_AHI 0
#define OFF_ALO (APL)
#define OFF_BHI (2 * APL)
#define OFF_BLO (3 * APL)
#define BUFSZ (4 * APL)                // 32 KB / stage
#define GEMM_SMEM (2 * BUFSZ)          // 64 KB

__global__ __launch_bounds__(256, 1)
void gemm_mma_kernel(const float* __restrict__ A, const float* __restrict__ Bt,
                     float* __restrict__ C, int M, int N, int K)
{
    extern __shared__ char sm[];
    const uint32_t sb = smem_u32(sm);
    const int tid = threadIdx.x;
    const int wid = tid >> 5, lane = tid & 31;
    const int m0 = blockIdx.y * GBM;
    const int n0 = blockIdx.x * GBN;
    const int wm = wid & 3;            // warp tile 32x64
    const int wn = wid >> 2;

    // gmem load slots: 128 rows x 32 floats, 4 float4 per thread
    const float* apt[4];
    const float* bpt[4];
    uint32_t asw[4];
#pragma unroll
    for (int i = 0; i < 4; i++) {
        int idx = tid + i * 256, r = idx >> 3, c = idx & 7;
        apt[i] = A + (size_t)(m0 + r) * K + c * 4;
        bpt[i] = Bt + (size_t)(n0 + r) * K + c * 4;
        asw[i] = SWZ64((uint32_t)(r * 64 + c * 8));
    }

    // A-frag geometry: lanes: row = base + (lane&15), chunk += lane>>4
    const int arowl = lane & 15;
    const int ca = lane >> 4;
    uint32_t a_rb[2]; int a_rx[2];
#pragma unroll
    for (int mi = 0; mi < 2; mi++) {
        int r = wm * 32 + mi * 16 + arowl;
        a_rb[mi] = (uint32_t)(r * 64); a_rx[mi] = (r >> 1) & 3;
    }
    // B-frag geometry: row = base + (lane&7) + ((lane>>4)<<3), chunk += (lane>>3)&1
    const int lrowb = (lane & 7) + ((lane >> 4) << 3);
    const int cb = (lane >> 3) & 1;
    uint32_t b_rb[4]; int b_rx[4];
#pragma unroll
    for (int bi = 0; bi < 4; bi++) {
        int r = wn * 64 + bi * 16 + lrowb;
        b_rb[bi] = (uint32_t)(r * 64); b_rx[bi] = (r >> 1) & 3;
    }

    float acc[2][8][4];
#pragma unroll
    for (int mi = 0; mi < 2; mi++)
#pragma unroll
        for (int ni = 0; ni < 8; ni++)
#pragma unroll
            for (int j = 0; j < 4; j++) acc[mi][ni][j] = 0.0f;

    float4 a4[4], b4[4];
#pragma unroll
    for (int i = 0; i < 4; i++) { a4[i] = *(const float4*)apt[i]; b4[i] = *(const float4*)bpt[i]; }
#pragma unroll
    for (int i = 0; i < 4; i++) {
        sts_split_h(a4[i], sb + OFF_AHI + asw[i], sb + OFF_ALO + asw[i]);
        sts_split_h(b4[i], sb + OFF_BHI + asw[i], sb + OFF_BLO + asw[i]);
    }
    __syncthreads();

    const int S = K / GBK;
    for (int s = 0; s < S; s++) {
        const int buf = s & 1;
        const uint32_t base = sb + buf * BUFSZ;

        if (s + 1 < S) {
            const int k0 = (s + 1) * GBK;
#pragma unroll
            for (int i = 0; i < 4; i++) {
                a4[i] = *(const float4*)(apt[i] + k0);
                b4[i] = *(const float4*)(bpt[i] + k0);
            }
        }

#pragma unroll
        for (int ks = 0; ks < 2; ks++) {
            uint32_t ah[2][4], al[2][4];
#pragma unroll
            for (int mi = 0; mi < 2; mi++) {
                uint32_t off = a_rb[mi] + (uint32_t)((((ks * 2 + ca) ^ a_rx[mi])) << 4);
                LDSM4(ah[mi], base + OFF_AHI + off);
                LDSM4(al[mi], base + OFF_ALO + off);
            }
#pragma unroll
            for (int nt = 0; nt < 4; nt++) {
                uint32_t bh[4], bl[4];
                uint32_t off = b_rb[nt] + (uint32_t)((((ks * 2 + cb) ^ b_rx[nt])) << 4);
                LDSM4(bh, base + OFF_BHI + off);
                LDSM4(bl, base + OFF_BLO + off);
#pragma unroll
                for (int mi = 0; mi < 2; mi++)
#pragma unroll
                    for (int j = 0; j < 2; j++) {
                        int ni = nt * 2 + j;
                        MMA_F16(acc[mi][ni], ah[mi], bh[j * 2], bh[j * 2 + 1]);
                        MMA_F16(acc[mi][ni], ah[mi], bl[j * 2], bl[j * 2 + 1]);
                        MMA_F16(acc[mi][ni], al[mi], bh[j * 2], bh[j * 2 + 1]);
                    }
            }
        }
        __syncthreads();

        if (s + 1 < S) {
            const uint32_t nb = sb + (buf ^ 1) * BUFSZ;
#pragma unroll
            for (int i = 0; i < 4; i++) {
                sts_split_h(a4[i], nb + OFF_AHI + asw[i], nb + OFF_ALO + asw[i]);
                sts_split_h(b4[i], nb + OFF_BHI + asw[i], nb + OFF_BLO + asw[i]);
            }
            __syncthreads();
        }
    }

#pragma unroll
    for (int mi = 0; mi < 2; mi++)
#pragma unroll
        for (int ni = 0; ni < 8; ni++) {
            int row = m0 + wm * 32 + mi * 16 + (lane >> 2);
            int col = n0 + wn * 64 + ni * 8 + (lane & 3) * 2;
            *(float2*)(C + (size_t)row * N + col) =
                make_float2(acc[mi][ni][0], acc[mi][ni][1]);
            *(float2*)(C + (size_t)(row + 8) * N + col) =
                make_float2(acc[mi][ni][2], acc[mi][ni][3]);
        }
}

// ---------------- transpose: out[C,R] = in[R,C]^T ---------------------------
__global__ void transpose_kernel(const float* __restrict__ in, float* __restrict__ out,
                                 int R, int C)
{
    __shared__ float t[32][33];
    const int bx = blockIdx.x * 32, by = blockIdx.y * 32;
    const int tx = threadIdx.x, ty = threadIdx.y;
#pragma unroll
    for (int j = 0; j < 32; j += 8)
        t[ty + j][tx] = in[(size_t)(by + ty + j) * C + bx + tx];
    __syncthreads();
#pragma unroll
    for (int j = 0; j < 32; j += 8)
        out[(size_t)(bx + ty + j) * R + by + tx] = t[tx][ty + j];
}

// ---------------- RoPE + per-head RMSNorm (one warp per (token, head)) ----
__global__ void rope_rms_kernel(float* __restrict__ buf,
                                const float* __restrict__ cosp,
                                const float* __restrict__ sinp,
                                int nheads)
{
    int gw = (blockIdx.x * blockDim.x + threadIdx.x) >> 5;
    int lane = threadIdx.x & 31;
    int total = TOK * nheads;
    if (gw >= total) return;
    int tok = gw / nheads;
    int l = tok % SEQ;

    float* p = buf + (size_t)gw * HD;
    float x1 = p[lane];
    float x2 = p[lane + 32];
    float c = cosp[l * 32 + lane];
    float s = sinp[l * 32 + lane];
    float o1 = x1 * c - x2 * s;
    float o2 = x2 * c + x1 * s;
    float ss = o1 * o1 + o2 * o2;
#pragma unroll
    for (int off = 16; off > 0; off >>= 1)
        ss += __shfl_xor_sync(0xffffffffu, ss, off);
    float r = rsqrtf(ss * (1.0f / 64.0f) + 1e-6f);
    p[lane] = o1 * r;
    p[lane + 32] = o2 * r;
}

// =============== Flash attention via 3xFP16 mma.sync =======================
// CTA: 128 queries, 8 warps, 16 q-rows/warp. Key tiles of 64.
// fp16 planes, 128-byte rows (64 halves), SW128 swizzle.
#define QHI_B 0u
#define QLO_B 16384u
#define KHI_B 32768u
#define KLO_B 40960u
#define VHI_B 49152u
#define VLO_B 57344u
#define PHI_B 65536u
#define PLO_B 81920u
#define ATTN_SMEM 98304

__global__ __launch_bounds__(256, 2) void attn_mma_kernel()
{
    extern __shared__ float smf[];
    const uint32_t sb = smem_u32(smf);
    const int qt = (int)gridDim.x - 1 - (int)blockIdx.x;  // heavy tiles first
    const int h = blockIdx.y, b = blockIdx.z;
    const int kvh = h >> 2;
    const int tid = threadIdx.x;
    const int warp = tid >> 5, lane = tid & 31;
    const int q0 = qt * 128;

    // ---- load Q tile (128x64 fp32) -> hi/lo fp16 planes ----
#pragma unroll
    for (int it = 0; it < 8; it++) {
        int idx = tid + it * 256;
        int row = idx >> 4, f4 = idx & 15;
        float4 v = *(const float4*)(g_q + (((size_t)(b * SEQ + q0 + row) * NH + h) << 6) + f4 * 4);
        uint32_t byte = SWZ((uint32_t)(row * 128 + f4 * 8));
        sts_split_h(v, sb + QHI_B + byte, sb + QLO_B + byte);
    }

    // fragment geometry
    const int arowl = lane & 15;          // A rows
    const int ca = lane >> 4;
    const int lrowb = (lane & 7) + ((lane >> 4) << 3);   // B rows
    const int cb = (lane >> 3) & 1;
    const int ar = warp * 16 + arowl;
    const uint32_t a_rb = (uint32_t)(ar * 128);
    const int a_rx = ar & 7;
    uint32_t b_rb[4]; int b_rx[4];
#pragma unroll
    for (int bi = 0; bi < 4; bi++) {
        int r = bi * 16 + lrowb;
        b_rb[bi] = (uint32_t)(r * 128); b_rx[bi] = r & 7;
    }

    float m0 = -1e30f, m1 = -1e30f, l0 = 0.f, l1 = 0.f;
    float oacc[8][4];
#pragma unroll
    for (int nt = 0; nt < 8; nt++)
#pragma unroll
        for (int j = 0; j < 4; j++) oacc[nt][j] = 0.f;

    const int rloc = lane >> 2;
    const int qrow0 = q0 + warp * 16 + rloc;
    const int qrow1 = qrow0 + 8;
    const int ktmax = 2 * qt + 1;

    for (int kt = 0; kt <= ktmax; kt++) {
        const int k0 = kt * 64;
        __syncthreads();
        // ---- load K (64x64) hi/lo; V transposed (Vt[dim][key]) hi/lo ----
#pragma unroll
        for (int it = 0; it < 4; it++) {
            int idx = tid + it * 256;
            int row = idx >> 4, f4 = idx & 15;
            size_t gi = (((size_t)(b * SEQ + k0 + row) * NKV + kvh) << 6) + f4 * 4;
            float4 kv = *(const float4*)(g_k + gi);
            uint32_t kb = SWZ((uint32_t)(row * 128 + f4 * 8));
            sts_split_h(kv, sb + KHI_B + kb, sb + KLO_B + kb);
            float4 vv = *(const float4*)(g_v + gi);
            float vals[4] = {vv.x, vv.y, vv.z, vv.w};
#pragma unroll
            for (int j = 0; j < 4; j++) {
                int dim = f4 * 4 + j;
                uint32_t vb = SWZ((uint32_t)(dim * 128 + row * 2));
                __half hv = __float2half_rn(vals[j]);
                __half lv = __float2half_rn(vals[j] - __half2float(hv));
                uint16_t hb = __half_as_ushort(hv), lb = __half_as_ushort(lv);
                asm volatile("st.shared.b16 [%0], %1;" :: "r"(sb + VHI_B + vb), "h"(hb) : "memory");
                asm volatile("st.shared.b16 [%0], %1;" :: "r"(sb + VLO_B + vb), "h"(lb) : "memory");
            }
        }
        __syncthreads();

        // ---- S = Q @ K^T ----
        float sacc[8][4];
#pragma unroll
        for (int nt = 0; nt < 8; nt++)
#pragma unroll
            for (int j = 0; j < 4; j++) sacc[nt][j] = 0.f;

#pragma unroll
        for (int ks = 0; ks < 4; ks++) {
            uint32_t qh[4], ql[4];
            uint32_t aoff = a_rb + (uint32_t)((((ks * 2 + ca) ^ a_rx)) << 4);
            LDSM4(qh, sb + QHI_B + aoff);
            LDSM4(ql, sb + QLO_B + aoff);
#pragma unroll
            for (int nt = 0; nt < 4; nt++) {
                uint32_t kh[4], kl[4];
                uint32_t boff = b_rb[nt] + (uint32_t)((((ks * 2 + cb) ^ b_rx[nt])) << 4);
                LDSM4(kh, sb + KHI_B + boff);
                LDSM4(kl, sb + KLO_B + boff);
#pragma unroll
                for (int j = 0; j < 2; j++) {
                    int ni = nt * 2 + j;
                    MMA_F16(sacc[ni], qh, kh[j * 2], kh[j * 2 + 1]);
                    MMA_F16(sacc[ni], qh, kl[j * 2], kl[j * 2 + 1]);
                    MMA_F16(sacc[ni], ql, kh[j * 2], kh[j * 2 + 1]);
                }
            }
        }

        // ---- online softmax ----
        const bool domask = (k0 + 63 > q0);
#pragma unroll
        for (int nt = 0; nt < 8; nt++) {
            int keyb = k0 + nt * 8 + (lane & 3) * 2;
#pragma unroll
            for (int j = 0; j < 4; j++) {
                float s = sacc[nt][j] * 0.125f;
                if (domask) {
                    int key = keyb + (j & 1);
                    int qq = (j < 2) ? qrow0 : qrow1;
                    if (key > qq) s = -1e30f;
                }
                sacc[nt][j] = s;
            }
        }
        float mx0 = -1e30f, mx1 = -1e30f;
#pragma unroll
        for (int nt = 0; nt < 8; nt++) {
            mx0 = fmaxf(mx0, fmaxf(sacc[nt][0], sacc[nt][1]));
            mx1 = fmaxf(mx1, fmaxf(sacc[nt][2], sacc[nt][3]));
        }
        mx0 = fmaxf(mx0, __shfl_xor_sync(0xffffffffu, mx0, 1));
        mx0 = fmaxf(mx0, __shfl_xor_sync(0xffffffffu, mx0, 2));
        mx1 = fmaxf(mx1, __shfl_xor_sync(0xffffffffu, mx1, 1));
        mx1 = fmaxf(mx1, __shfl_xor_sync(0xffffffffu, mx1, 2));
        float nm0 = fmaxf(m0, mx0), nm1 = fmaxf(m1, mx1);
        float c0 = __expf(m0 - nm0), c1 = __expf(m1 - nm1);
        m0 = nm0; m1 = nm1;
        float rs0 = 0.f, rs1 = 0.f;
#pragma unroll
        for (int nt = 0; nt < 8; nt++) {
            float p0 = __expf(sacc[nt][0] - nm0);
            float p1 = __expf(sacc[nt][1] - nm0);
            float p2 = __expf(sacc[nt][2] - nm1);
            float p3 = __expf(sacc[nt][3] - nm1);
            sacc[nt][0] = p0; sacc[nt][1] = p1; sacc[nt][2] = p2; sacc[nt][3] = p3;
            rs0 += p0 + p1; rs1 += p2 + p3;
        }
        rs0 += __shfl_xor_sync(0xffffffffu, rs0, 1);
        rs0 += __shfl_xor_sync(0xffffffffu, rs0, 2);
        rs1 += __shfl_xor_sync(0xffffffffu, rs1, 1);
        rs1 += __shfl_xor_sync(0xffffffffu, rs1, 2);
        l0 = l0 * c0 + rs0;
        l1 = l1 * c1 + rs1;
#pragma unroll
        for (int nt = 0; nt < 8; nt++) {
            oacc[nt][0] *= c0; oacc[nt][1] *= c0;
            oacc[nt][2] *= c1; oacc[nt][3] *= c1;
        }

        // ---- store P hi/lo (this warp's 16 rows) ----
        const int prow0 = warp * 16 + rloc;
#pragma unroll
        for (int nt = 0; nt < 8; nt++) {
            int keyl = nt * 8 + (lane & 3) * 2;
            uint32_t by0 = SWZ((uint32_t)(prow0 * 128 + keyl * 2));
            uint32_t by1 = SWZ((uint32_t)((prow0 + 8) * 128 + keyl * 2));
            uint32_t hp, lp;
            split_pair(sacc[nt][0], sacc[nt][1], hp, lp);
            asm volatile("st.shared.b32 [%0], %1;" :: "r"(sb + PHI_B + by0), "r"(hp) : "memory");
            asm volatile("st.shared.b32 [%0], %1;" :: "r"(sb + PLO_B + by0), "r"(lp) : "memory");
            split_pair(sacc[nt][2], sacc[nt][3], hp, lp);
            asm volatile("st.shared.b32 [%0], %1;" :: "r"(sb + PHI_B + by1), "r"(hp) : "memory");
            asm volatile("st.shared.b32 [%0], %1;" :: "r"(sb + PLO_B + by1), "r"(lp) : "memory");
        }
        __syncwarp();

        // ---- O += P @ V ----
#pragma unroll
        for (int ks = 0; ks < 4; ks++) {
            uint32_t ph[4], pl[4];
            uint32_t aoff = a_rb + (uint32_t)((((ks * 2 + ca) ^ a_rx)) << 4);
            LDSM4(ph, sb + PHI_B + aoff);
            LDSM4(pl, sb + PLO_B + aoff);
#pragma unroll
            for (int nt = 0; nt < 4; nt++) {
                uint32_t vh[4], vl[4];
                uint32_t boff = b_rb[nt] + (uint32_t)((((ks * 2 + cb) ^ b_rx[nt])) << 4);
                LDSM4(vh, sb + VHI_B + boff);
                LDSM4(vl, sb + VLO_B + boff);
#pragma unroll
                for (int j = 0; j < 2; j++) {
                    int ni = nt * 2 + j;
                    MMA_F16(oacc[ni], ph, vh[j * 2], vh[j * 2 + 1]);
                    MMA_F16(oacc[ni], ph, vl[j * 2], vl[j * 2 + 1]);
                    MMA_F16(oacc[ni], pl, vh[j * 2], vh[j * 2 + 1]);
                }
            }
        }
    }

    // ---- epilogue ----
    float inv0 = 1.0f / l0, inv1 = 1.0f / l1;
    size_t o0 = (((size_t)(b * SEQ + qrow0) * NH + h) << 6);
    size_t o1 = (((size_t)(b * SEQ + qrow1) * NH + h) << 6);
#pragma unroll
    for (int nt = 0; nt < 8; nt++) {
        int dim = nt * 8 + (lane & 3) * 2;
        *(float2*)(g_o + o0 + dim) = make_float2(oacc[nt][0] * inv0, oacc[nt][1] * inv0);
        *(float2*)(g_o + o1 + dim) = make_float2(oacc[nt][2] * inv1, oacc[nt][3] * inv1);
    }
}

// ---------------- launch ---------------------------------------------------
extern "C" void kernel_launch(void* const* d_in, const int* in_sizes, int n_in,
                              void* d_out, int out_size)
{
    const float* x    = (const float*)d_in[0];
    const float* cosp = (const float*)d_in[1];
    const float* sinp = (const float*)d_in[2];
    const float* Wq   = (const float*)d_in[3];
    const float* Wk   = (const float*)d_in[4];
    const float* Wv   = (const float*)d_in[5];
    const float* Wo   = (const float*)d_in[6];
    float* out = (float*)d_out;

    float *q, *k, *v, *o, *wqt, *wkt, *wvt, *wot;
    cudaGetSymbolAddress((void**)&q, g_q);
    cudaGetSymbolAddress((void**)&k, g_k);
    cudaGetSymbolAddress((void**)&v, g_v);
    cudaGetSymbolAddress((void**)&o, g_o);
    cudaGetSymbolAddress((void**)&wqt, g_wqt);
    cudaGetSymbolAddress((void**)&wkt, g_wkt);
    cudaGetSymbolAddress((void**)&wvt, g_wvt);
    cudaGetSymbolAddress((void**)&wot, g_wot);

    cudaFuncSetAttribute(gemm_mma_kernel,
                         cudaFuncAttributeMaxDynamicSharedMemorySize, GEMM_SMEM);
    cudaFuncSetAttribute(attn_mma_kernel,
                         cudaFuncAttributeMaxDynamicSharedMemorySize, ATTN_SMEM);

    // transpose weights -> [N, K] K-major
    dim3 tb(32, 8);
    transpose_kernel<<<dim3(D_MODEL / 32, D_MODEL / 32), tb>>>(Wq, wqt, D_MODEL, D_MODEL);
    transpose_kernel<<<dim3((NKV * HD) / 32, D_MODEL / 32), tb>>>(Wk, wkt, D_MODEL, NKV * HD);
    transpose_kernel<<<dim3((NKV * HD) / 32, D_MODEL / 32), tb>>>(Wv, wvt, D_MODEL, NKV * HD);
    transpose_kernel<<<dim3(D_MODEL / 32, D_MODEL / 32), tb>>>(Wo, wot, D_MODEL, D_MODEL);

    // projections (mma.sync fp16, hi/lo split)
    gemm_mma_kernel<<<dim3(D_MODEL / GBN, TOK / GBM), 256, GEMM_SMEM>>>(
        x, wqt, q, TOK, D_MODEL, D_MODEL);
    gemm_mma_kernel<<<dim3((NKV * HD) / GBN, TOK / GBM), 256, GEMM_SMEM>>>(
        x, wkt, k, TOK, NKV * HD, D_MODEL);
    gemm_mma_kernel<<<dim3((NKV * HD) / GBN, TOK / GBM), 256, GEMM_SMEM>>>(
        x, wvt, v, TOK, NKV * HD, D_MODEL);

    rope_rms_kernel<<<(TOK * NH) / 8, 256>>>(q, cosp, sinp, NH);
    rope_rms_kernel<<<(TOK * NKV) / 8, 256>>>(k, cosp, sinp, NKV);

    // attention (mma.sync fp16 flash attention)
    attn_mma_kernel<<<dim3(SEQ / 128, NH, BATCH), 256, ATTN_SMEM>>>();

    gemm_mma_kernel<<<dim3(D_MODEL / GBN, TOK / GBM), 256, GEMM_SMEM>>>(
        o, wot, out, TOK, D_MODEL, D_MODEL);
}

// round 7
// speedup vs baseline: 3.1444x; 1.1426x over previous
#include <cuda_runtime.h>
#include <cuda_fp16.h>
#include <math.h>
#include <stdint.h>

#define D_MODEL 2048
#define NH 32
#define NKV 8
#define HD 64
#define BATCH 2
#define SEQ 2048
#define TOK (BATCH * SEQ)   // 4096
#define KVD (NKV * HD)      // 512

// ---------------- scratch (device globals; no allocation allowed) ----------
__device__ float  g_q[(size_t)TOK * NH * HD];     // fp32 q after projection
__device__ float  g_k[(size_t)TOK * NKV * HD];
__device__ float  g_v[(size_t)TOK * NKV * HD];
__device__ __half g_xh[(size_t)TOK * D_MODEL];    // x hi/lo planes
__device__ __half g_xl[(size_t)TOK * D_MODEL];
__device__ __half g_wqth[(size_t)D_MODEL * D_MODEL];
__device__ __half g_wqtl[(size_t)D_MODEL * D_MODEL];
__device__ __half g_wkth[(size_t)KVD * D_MODEL];
__device__ __half g_wktl[(size_t)KVD * D_MODEL];
__device__ __half g_wvth[(size_t)KVD * D_MODEL];
__device__ __half g_wvtl[(size_t)KVD * D_MODEL];
__device__ __half g_woth[(size_t)D_MODEL * D_MODEL];
__device__ __half g_wotl[(size_t)D_MODEL * D_MODEL];
__device__ __half g_qh[(size_t)TOK * NH * HD];    // q planes after rope+rms
__device__ __half g_ql[(size_t)TOK * NH * HD];
__device__ __half g_kh[(size_t)TOK * NKV * HD];
__device__ __half g_kl[(size_t)TOK * NKV * HD];
__device__ __half g_vth[(size_t)BATCH * NKV * HD * SEQ];  // V transposed planes
__device__ __half g_vtl[(size_t)BATCH * NKV * HD * SEQ];
__device__ __half g_oh[(size_t)TOK * NH * HD];    // attention output planes
__device__ __half g_ol[(size_t)TOK * NH * HD];

// ======================= helpers (portable PTX only) ========================
__device__ __forceinline__ uint32_t smem_u32(const void* p) {
    uint32_t a;
    asm("{ .reg .u64 t; cvta.to.shared.u64 t, %1; cvt.u32.u64 %0, t; }"
        : "=r"(a) : "l"(p));
    return a;
}
#define SWZ(o)   ((o) ^ (((o) >> 3) & 0x70))   // 128-byte rows
#define SWZ64(o) ((o) ^ (((o) >> 3) & 0x30))   // 64-byte rows

#define LDSM4(r, a) \
    asm volatile("ldmatrix.sync.aligned.m8n8.x4.shared.b16 {%0,%1,%2,%3}, [%4];" \
        : "=r"((r)[0]), "=r"((r)[1]), "=r"((r)[2]), "=r"((r)[3]) : "r"(a))

#define MMA_F16(c, a, b0, b1) \
    asm volatile("mma.sync.aligned.m16n8k16.row.col.f32.f16.f16.f32 " \
        "{%0,%1,%2,%3}, {%4,%5,%6,%7}, {%8,%9}, {%0,%1,%2,%3};" \
        : "+f"((c)[0]), "+f"((c)[1]), "+f"((c)[2]), "+f"((c)[3]) \
        : "r"((a)[0]), "r"((a)[1]), "r"((a)[2]), "r"((a)[3]), \
          "r"(b0), "r"(b1))

#define CP16(dst, src) \
    asm volatile("cp.async.ca.shared.global [%0], [%1], 16;" \
                 :: "r"(dst), "l"(src) : "memory")
#define CP_COMMIT() asm volatile("cp.async.commit_group;" ::: "memory")
#define CP_WAIT0()  asm volatile("cp.async.wait_group 0;" ::: "memory")

__device__ __forceinline__ uint32_t packh2(__half a, __half b) {
    __half2 t = __halves2half2(a, b);
    return *(uint32_t*)&t;
}
__device__ __forceinline__ void split_pair(float f0, float f1,
                                           uint32_t& hp, uint32_t& lp) {
    __half h0 = __float2half_rn(f0), h1 = __float2half_rn(f1);
    __half l0 = __float2half_rn(f0 - __half2float(h0));
    __half l1 = __float2half_rn(f1 - __half2float(h1));
    hp = packh2(h0, h1); lp = packh2(l0, l1);
}

// ---------------- elementwise split: fp32 -> hi/lo fp16 planes -------------
__global__ void split_kernel(const float* __restrict__ in,
                             __half* __restrict__ hi, __half* __restrict__ lo,
                             int n4)
{
    int i = blockIdx.x * blockDim.x + threadIdx.x;
    if (i >= n4) return;
    float4 v = ((const float4*)in)[i];
    uint32_t h01, l01, h23, l23;
    split_pair(v.x, v.y, h01, l01);
    split_pair(v.z, v.w, h23, l23);
    ((uint2*)hi)[i] = make_uint2(h01, h23);
    ((uint2*)lo)[i] = make_uint2(l01, l23);
}

// ---------------- transpose + split: W[K,N] fp32 -> Wt hi/lo [N,K] half ----
__global__ void wsplit_t_kernel(const float* __restrict__ in,
                                __half* __restrict__ hi, __half* __restrict__ lo,
                                int R, int C)   // in is [R,C]; out [C,R]
{
    __shared__ float t[32][33];
    const int bx = blockIdx.x * 32, by = blockIdx.y * 32;
    const int tx = threadIdx.x, ty = threadIdx.y;
#pragma unroll
    for (int j = 0; j < 32; j += 8)
        t[ty + j][tx] = in[(size_t)(by + ty + j) * C + bx + tx];
    __syncthreads();
#pragma unroll
    for (int j = 0; j < 32; j += 8) {
        float f = t[tx][ty + j];
        __half h = __float2half_rn(f);
        size_t o = (size_t)(bx + ty + j) * R + by + tx;
        hi[o] = h;
        lo[o] = __float2half_rn(f - __half2float(h));
    }
}

// ---------------- V: split + transpose -> Vt[b][kvh][dim][seq] -------------
__global__ void vsplit_t_kernel()
{
    __shared__ float t[32][33];
    const int bkv = blockIdx.z;             // b*NKV + kvh
    const int b = bkv >> 3, kvh = bkv & 7;
    const int s0 = blockIdx.y * 32;         // seq tile
    const int d0 = blockIdx.x * 32;         // dim tile
    const int tx = threadIdx.x, ty = threadIdx.y;
#pragma unroll
    for (int j = 0; j < 32; j += 8)
        t[ty + j][tx] = g_v[(((size_t)(b * SEQ + s0 + ty + j) * NKV + kvh) << 6) + d0 + tx];
    __syncthreads();
#pragma unroll
    for (int j = 0; j < 32; j += 8) {
        float f = t[tx][ty + j];
        __half h = __float2half_rn(f);
        size_t o = ((size_t)(bkv * HD) + d0 + ty + j) * SEQ + s0 + tx;
        g_vth[o] = h;
        g_vtl[o] = __float2half_rn(f - __half2float(h));
    }
}

// ---------------- RoPE + RMSNorm, writes hi/lo fp16 planes -----------------
__global__ void rope_rms_split_kernel(const float* __restrict__ src,
                                      __half* __restrict__ hi, __half* __restrict__ lo,
                                      const float* __restrict__ cosp,
                                      const float* __restrict__ sinp,
                                      int nheads)
{
    int gw = (blockIdx.x * blockDim.x + threadIdx.x) >> 5;
    int lane = threadIdx.x & 31;
    int total = TOK * nheads;
    if (gw >= total) return;
    int tok = gw / nheads;
    int l = tok % SEQ;

    const float* p = src + (size_t)gw * HD;
    float x1 = p[lane];
    float x2 = p[lane + 32];
    float c = cosp[l * 32 + lane];
    float s = sinp[l * 32 + lane];
    float o1 = x1 * c - x2 * s;
    float o2 = x2 * c + x1 * s;
    float ss = o1 * o1 + o2 * o2;
#pragma unroll
    for (int off = 16; off > 0; off >>= 1)
        ss += __shfl_xor_sync(0xffffffffu, ss, off);
    float r = rsqrtf(ss * (1.0f / 64.0f) + 1e-6f);
    o1 *= r; o2 *= r;
    __half h1 = __float2half_rn(o1), h2 = __float2half_rn(o2);
    hi[(size_t)gw * HD + lane] = h1;
    hi[(size_t)gw * HD + lane + 32] = h2;
    lo[(size_t)gw * HD + lane] = __float2half_rn(o1 - __half2float(h1));
    lo[(size_t)gw * HD + lane + 32] = __float2half_rn(o2 - __half2float(h2));
}

// ======================= 3xFP16 GEMM, cp.async pipeline =====================
// C[M,N] = (Ah+Al)[M,K] @ (Bh+Bl)[N,K]^T (hh+hl+lh). CTA 128x128, BK=32.
#define GBM 128
#define GBN 128
#define GBK 32
#define APL 8192                       // one plane: 128 rows * 64 B
#define OFF_AHI 0
#define OFF_ALO (APL)
#define OFF_BHI (2 * APL)
#define OFF_BLO (3 * APL)
#define BUFSZ (4 * APL)                // 32 KB / stage
#define GEMM_SMEM (2 * BUFSZ)          // 64 KB

__global__ __launch_bounds__(256, 2)
void gemm_mma_kernel(const __half* __restrict__ Ah, const __half* __restrict__ Al,
                     const __half* __restrict__ Bh, const __half* __restrict__ Bl,
                     float* __restrict__ C, int M, int N, int K)
{
    extern __shared__ char sm[];
    const uint32_t sb = smem_u32(sm);
    const int tid = threadIdx.x;
    const int wid = tid >> 5, lane = tid & 31;
    const int m0 = blockIdx.y * GBM;
    const int n0 = blockIdx.x * GBN;
    const int wm = wid & 3;
    const int wn = wid >> 2;

    // cp.async slots: 2048 chunks of 16B (4 planes x 128 rows x 4), 8/thread
    const __half* srcs[8];
    uint32_t dsts[8];
#pragma unroll
    for (int i = 0; i < 8; i++) {
        int gidx = tid + i * 256;
        int plane = gidx >> 9;              // 0 AHI, 1 ALO, 2 BHI, 3 BLO
        int c = gidx & 511;
        int r = c >> 2, q = c & 3;
        const __half* base = (plane == 0) ? Ah : (plane == 1) ? Al
                           : (plane == 2) ? Bh : Bl;
        int row = (plane < 2 ? m0 : n0) + r;
        srcs[i] = base + (size_t)row * K + q * 8;
        dsts[i] = (uint32_t)(plane * APL) + SWZ64((uint32_t)(r * 64 + q * 16));
    }

    // fragment geometry (fp16 canonical)
    const int arowl = lane & 15;
    const int ca = lane >> 4;
    uint32_t a_rb[2]; int a_rx[2];
#pragma unroll
    for (int mi = 0; mi < 2; mi++) {
        int r = wm * 32 + mi * 16 + arowl;
        a_rb[mi] = (uint32_t)(r * 64); a_rx[mi] = (r >> 1) & 3;
    }
    const int lrowb = (lane & 7) + ((lane >> 4) << 3);
    const int cb = (lane >> 3) & 1;
    uint32_t b_rb[4]; int b_rx[4];
#pragma unroll
    for (int bi = 0; bi < 4; bi++) {
        int r = wn * 64 + bi * 16 + lrowb;
        b_rb[bi] = (uint32_t)(r * 64); b_rx[bi] = (r >> 1) & 3;
    }

    float acc[2][8][4];
#pragma unroll
    for (int mi = 0; mi < 2; mi++)
#pragma unroll
        for (int ni = 0; ni < 8; ni++)
#pragma unroll
            for (int j = 0; j < 4; j++) acc[mi][ni][j] = 0.0f;

    // prologue: stage 0
#pragma unroll
    for (int i = 0; i < 8; i++) CP16(sb + dsts[i], srcs[i]);
    CP_COMMIT();
    CP_WAIT0();
    __syncthreads();

    const int S = K / GBK;
    for (int s = 0; s < S; s++) {
        const uint32_t base = sb + (uint32_t)(s & 1) * BUFSZ;

        if (s + 1 < S) {
            const uint32_t nb = (uint32_t)((s + 1) & 1) * BUFSZ;
            const int k0 = (s + 1) * GBK;
#pragma unroll
            for (int i = 0; i < 8; i++) CP16(sb + nb + dsts[i], srcs[i] + k0);
            CP_COMMIT();
        }

#pragma unroll
        for (int ks = 0; ks < 2; ks++) {
            uint32_t ah[2][4], al[2][4];
#pragma unroll
            for (int mi = 0; mi < 2; mi++) {
                uint32_t off = a_rb[mi] + (uint32_t)((((ks * 2 + ca) ^ a_rx[mi])) << 4);
                LDSM4(ah[mi], base + OFF_AHI + off);
                LDSM4(al[mi], base + OFF_ALO + off);
            }
#pragma unroll
            for (int nt = 0; nt < 4; nt++) {
                uint32_t bh[4], bl[4];
                uint32_t off = b_rb[nt] + (uint32_t)((((ks * 2 + cb) ^ b_rx[nt])) << 4);
                LDSM4(bh, base + OFF_BHI + off);
                LDSM4(bl, base + OFF_BLO + off);
#pragma unroll
                for (int j = 0; j < 2; j++) {
                    int ni = nt * 2 + j;
#pragma unroll
                    for (int mi = 0; mi < 2; mi++) {
                        MMA_F16(acc[mi][ni], ah[mi], bh[j * 2], bh[j * 2 + 1]);
                        MMA_F16(acc[mi][ni], ah[mi], bl[j * 2], bl[j * 2 + 1]);
                        MMA_F16(acc[mi][ni], al[mi], bh[j * 2], bh[j * 2 + 1]);
                    }
                }
            }
        }

        if (s + 1 < S) {
            CP_WAIT0();
            __syncthreads();
        }
    }

#pragma unroll
    for (int mi = 0; mi < 2; mi++)
#pragma unroll
        for (int ni = 0; ni < 8; ni++) {
            int row = m0 + wm * 32 + mi * 16 + (lane >> 2);
            int col = n0 + wn * 64 + ni * 8 + (lane & 3) * 2;
            *(float2*)(C + (size_t)row * N + col) =
                make_float2(acc[mi][ni][0], acc[mi][ni][1]);
            *(float2*)(C + (size_t)(row + 8) * N + col) =
                make_float2(acc[mi][ni][2], acc[mi][ni][3]);
        }
}

// =============== Flash attention, pre-split fp16 planes + cp.async =========
#define QHI_B 0u
#define QLO_B 16384u
#define KHI_B 32768u
#define VHI_B 49152u        // K planes: KHI 32768, KLO 40960; V: VHI 49152, VLO 57344
#define PHI_B 65536u
#define PLO_B 81920u
#define ATTN_SMEM 98304

__global__ __launch_bounds__(256, 2) void attn_mma_kernel()
{
    extern __shared__ float smf[];
    const uint32_t sb = smem_u32(smf);
    const int qt = (int)gridDim.x - 1 - (int)blockIdx.x;
    const int h = blockIdx.y, b = blockIdx.z;
    const int kvh = h >> 2;
    const int tid = threadIdx.x;
    const int warp = tid >> 5, lane = tid & 31;
    const int q0 = qt * 128;

    // ---- Q planes: 2048 chunks (2 planes x 128 rows x 8), 8/thread ----
#pragma unroll
    for (int i = 0; i < 8; i++) {
        int gidx = tid + i * 256;
        int plane = gidx >> 10;
        int c = gidx & 1023;
        int r = c >> 3, q = c & 7;
        const __half* src = (plane ? g_ql : g_qh)
            + (((size_t)(b * SEQ + q0 + r) * NH + h) << 6) + q * 8;
        CP16(sb + QHI_B + (uint32_t)plane * 16384u + SWZ((uint32_t)(r * 128 + q * 16)), src);
    }
    CP_COMMIT();

    // K/V per-tile cp.async slots: 2048 chunks (4 planes x 64 rows x 8)
    const __half* kv_src[8];
    uint32_t kv_dst[8];
    int kv_step[8];     // per-tile source advance (half units)
#pragma unroll
    for (int i = 0; i < 8; i++) {
        int gidx = tid + i * 256;
        int plane = gidx >> 9;            // 0 KHI, 1 KLO, 2 VHI, 3 VLO
        int c = gidx & 511;
        int r = c >> 3, q = c & 7;
        if (plane < 2) {
            kv_src[i] = (plane ? g_kl : g_kh)
                + (((size_t)(b * SEQ + r) * NKV + kvh) << 6) + q * 8;
            kv_step[i] = NKV * HD;        // per key row
        } else {
            kv_src[i] = ((plane == 3) ? g_vtl : g_vth)
                + ((size_t)((b * NKV + kvh) * HD) + r) * SEQ + q * 8;
            kv_step[i] = 1;
        }
        kv_dst[i] = KHI_B + (uint32_t)plane * 8192u + SWZ((uint32_t)(r * 128 + q * 16));
    }

    // fragment geometry
    const int arowl = lane & 15;
    const int ca = lane >> 4;
    const int lrowb = (lane & 7) + ((lane >> 4) << 3);
    const int cb = (lane >> 3) & 1;
    const int ar = warp * 16 + arowl;
    const uint32_t a_rb = (uint32_t)(ar * 128);
    const int a_rx = ar & 7;
    uint32_t b_rb[4]; int b_rx[4];
#pragma unroll
    for (int bi = 0; bi < 4; bi++) {
        int r = bi * 16 + lrowb;
        b_rb[bi] = (uint32_t)(r * 128); b_rx[bi] = r & 7;
    }

    float m0 = -1e30f, m1 = -1e30f, l0 = 0.f, l1 = 0.f;
    float oacc[8][4];
#pragma unroll
    for (int nt = 0; nt < 8; nt++)
#pragma unroll
        for (int j = 0; j < 4; j++) oacc[nt][j] = 0.f;

    const int rloc = lane >> 2;
    const int qrow0 = q0 + warp * 16 + rloc;
    const int qrow1 = qrow0 + 8;
    const int ktmax = 2 * qt + 1;

    for (int kt = 0; kt <= ktmax; kt++) {
        const int k0 = kt * 64;
        __syncthreads();               // prev tile consumers done with K/V smem
#pragma unroll
        for (int i = 0; i < 8; i++)
            CP16(sb + kv_dst[i], kv_src[i] + (size_t)k0 * kv_step[i]);
        CP_COMMIT();
        CP_WAIT0();
        __syncthreads();

        // ---- S = Q @ K^T ----
        float sacc[8][4];
#pragma unroll
        for (int nt = 0; nt < 8; nt++)
#pragma unroll
            for (int j = 0; j < 4; j++) sacc[nt][j] = 0.f;

#pragma unroll
        for (int ks = 0; ks < 4; ks++) {
            uint32_t qh[4], ql[4];
            uint32_t aoff = a_rb + (uint32_t)((((ks * 2 + ca) ^ a_rx)) << 4);
            LDSM4(qh, sb + QHI_B + aoff);
            LDSM4(ql, sb + QLO_B + aoff);
#pragma unroll
            for (int nt = 0; nt < 4; nt++) {
                uint32_t kh[4], kl[4];
                uint32_t boff = b_rb[nt] + (uint32_t)((((ks * 2 + cb) ^ b_rx[nt])) << 4);
                LDSM4(kh, sb + KHI_B + boff);
                LDSM4(kl, sb + KHI_B + 8192u + boff);
#pragma unroll
                for (int j = 0; j < 2; j++) {
                    int ni = nt * 2 + j;
                    MMA_F16(sacc[ni], qh, kh[j * 2], kh[j * 2 + 1]);
                    MMA_F16(sacc[ni], qh, kl[j * 2], kl[j * 2 + 1]);
                    MMA_F16(sacc[ni], ql, kh[j * 2], kh[j * 2 + 1]);
                }
            }
        }

        // ---- online softmax ----
        const bool domask = (k0 + 63 > q0);
#pragma unroll
        for (int nt = 0; nt < 8; nt++) {
            int keyb = k0 + nt * 8 + (lane & 3) * 2;
#pragma unroll
            for (int j = 0; j < 4; j++) {
                float s = sacc[nt][j] * 0.125f;
                if (domask) {
                    int key = keyb + (j & 1);
                    int qq = (j < 2) ? qrow0 : qrow1;
                    if (key > qq) s = -1e30f;
                }
                sacc[nt][j] = s;
            }
        }
        float mx0 = -1e30f, mx1 = -1e30f;
#pragma unroll
        for (int nt = 0; nt < 8; nt++) {
            mx0 = fmaxf(mx0, fmaxf(sacc[nt][0], sacc[nt][1]));
            mx1 = fmaxf(mx1, fmaxf(sacc[nt][2], sacc[nt][3]));
        }
        mx0 = fmaxf(mx0, __shfl_xor_sync(0xffffffffu, mx0, 1));
        mx0 = fmaxf(mx0, __shfl_xor_sync(0xffffffffu, mx0, 2));
        mx1 = fmaxf(mx1, __shfl_xor_sync(0xffffffffu, mx1, 1));
        mx1 = fmaxf(mx1, __shfl_xor_sync(0xffffffffu, mx1, 2));
        float nm0 = fmaxf(m0, mx0), nm1 = fmaxf(m1, mx1);
        float c0 = __expf(m0 - nm0), c1 = __expf(m1 - nm1);
        m0 = nm0; m1 = nm1;
        float rs0 = 0.f, rs1 = 0.f;
#pragma unroll
        for (int nt = 0; nt < 8; nt++) {
            float p0 = __expf(sacc[nt][0] - nm0);
            float p1 = __expf(sacc[nt][1] - nm0);
            float p2 = __expf(sacc[nt][2] - nm1);
            float p3 = __expf(sacc[nt][3] - nm1);
            sacc[nt][0] = p0; sacc[nt][1] = p1; sacc[nt][2] = p2; sacc[nt][3] = p3;
            rs0 += p0 + p1; rs1 += p2 + p3;
        }
        rs0 += __shfl_xor_sync(0xffffffffu, rs0, 1);
        rs0 += __shfl_xor_sync(0xffffffffu, rs0, 2);
        rs1 += __shfl_xor_sync(0xffffffffu, rs1, 1);
        rs1 += __shfl_xor_sync(0xffffffffu, rs1, 2);
        l0 = l0 * c0 + rs0;
        l1 = l1 * c1 + rs1;
#pragma unroll
        for (int nt = 0; nt < 8; nt++) {
            oacc[nt][0] *= c0; oacc[nt][1] *= c0;
            oacc[nt][2] *= c1; oacc[nt][3] *= c1;
        }

        // ---- store P hi/lo (this warp's 16 rows) ----
        const int prow0 = warp * 16 + rloc;
#pragma unroll
        for (int nt = 0; nt < 8; nt++) {
            int keyl = nt * 8 + (lane & 3) * 2;
            uint32_t by0 = SWZ((uint32_t)(prow0 * 128 + keyl * 2));
            uint32_t by1 = SWZ((uint32_t)((prow0 + 8) * 128 + keyl * 2));
            uint32_t hp, lp;
            split_pair(sacc[nt][0], sacc[nt][1], hp, lp);
            asm volatile("st.shared.b32 [%0], %1;" :: "r"(sb + PHI_B + by0), "r"(hp) : "memory");
            asm volatile("st.shared.b32 [%0], %1;" :: "r"(sb + PLO_B + by0), "r"(lp) : "memory");
            split_pair(sacc[nt][2], sacc[nt][3], hp, lp);
            asm volatile("st.shared.b32 [%0], %1;" :: "r"(sb + PHI_B + by1), "r"(hp) : "memory");
            asm volatile("st.shared.b32 [%0], %1;" :: "r"(sb + PLO_B + by1), "r"(lp) : "memory");
        }
        __syncwarp();

        // ---- O += P @ V ----
#pragma unroll
        for (int ks = 0; ks < 4; ks++) {
            uint32_t ph[4], pl[4];
            uint32_t aoff = a_rb + (uint32_t)((((ks * 2 + ca) ^ a_rx)) << 4);
            LDSM4(ph, sb + PHI_B + aoff);
            LDSM4(pl, sb + PLO_B + aoff);
#pragma unroll
            for (int nt = 0; nt < 4; nt++) {
                uint32_t vh[4], vl[4];
                uint32_t boff = b_rb[nt] + (uint32_t)((((ks * 2 + cb) ^ b_rx[nt])) << 4);
                LDSM4(vh, sb + VHI_B + boff);
                LDSM4(vl, sb + VHI_B + 8192u + boff);
#pragma unroll
                for (int j = 0; j < 2; j++) {
                    int ni = nt * 2 + j;
                    MMA_F16(oacc[ni], ph, vh[j * 2], vh[j * 2 + 1]);
                    MMA_F16(oacc[ni], ph, vl[j * 2], vl[j * 2 + 1]);
                    MMA_F16(oacc[ni], pl, vh[j * 2], vh[j * 2 + 1]);
                }
            }
        }
    }

    // ---- epilogue: normalize + split into o planes ----
    float inv0 = 1.0f / l0, inv1 = 1.0f / l1;
    size_t o0 = (((size_t)(b * SEQ + qrow0) * NH + h) << 6);
    size_t o1 = (((size_t)(b * SEQ + qrow1) * NH + h) << 6);
#pragma unroll
    for (int nt = 0; nt < 8; nt++) {
        int dim = nt * 8 + (lane & 3) * 2;
        uint32_t hp, lp;
        split_pair(oacc[nt][0] * inv0, oacc[nt][1] * inv0, hp, lp);
        *(uint32_t*)(g_oh + o0 + dim) = hp;
        *(uint32_t*)(g_ol + o0 + dim) = lp;
        split_pair(oacc[nt][2] * inv1, oacc[nt][3] * inv1, hp, lp);
        *(uint32_t*)(g_oh + o1 + dim) = hp;
        *(uint32_t*)(g_ol + o1 + dim) = lp;
    }
}

// ---------------- launch ---------------------------------------------------
extern "C" void kernel_launch(void* const* d_in, const int* in_sizes, int n_in,
                              void* d_out, int out_size)
{
    const float* x    = (const float*)d_in[0];
    const float* cosp = (const float*)d_in[1];
    const float* sinp = (const float*)d_in[2];
    const float* Wq   = (const float*)d_in[3];
    const float* Wk   = (const float*)d_in[4];
    const float* Wv   = (const float*)d_in[5];
    const float* Wo   = (const float*)d_in[6];
    float* out = (float*)d_out;

    float *q, *k, *v;
    __half *xh, *xl, *wqth, *wqtl, *wkth, *wktl, *wvth, *wvtl, *woth, *wotl;
    __half *qh, *ql, *kh, *kl, *oh, *ol;
    cudaGetSymbolAddress((void**)&q, g_q);
    cudaGetSymbolAddress((void**)&k, g_k);
    cudaGetSymbolAddress((void**)&v, g_v);
    cudaGetSymbolAddress((void**)&xh, g_xh);
    cudaGetSymbolAddress((void**)&xl, g_xl);
    cudaGetSymbolAddress((void**)&wqth, g_wqth);
    cudaGetSymbolAddress((void**)&wqtl, g_wqtl);
    cudaGetSymbolAddress((void**)&wkth, g_wkth);
    cudaGetSymbolAddress((void**)&wktl, g_wktl);
    cudaGetSymbolAddress((void**)&wvth, g_wvth);
    cudaGetSymbolAddress((void**)&wvtl, g_wvtl);
    cudaGetSymbolAddress((void**)&woth, g_woth);
    cudaGetSymbolAddress((void**)&wotl, g_wotl);
    cudaGetSymbolAddress((void**)&qh, g_qh);
    cudaGetSymbolAddress((void**)&ql, g_ql);
    cudaGetSymbolAddress((void**)&kh, g_kh);
    cudaGetSymbolAddress((void**)&kl, g_kl);
    cudaGetSymbolAddress((void**)&oh, g_oh);
    cudaGetSymbolAddress((void**)&ol, g_ol);

    cudaFuncSetAttribute(gemm_mma_kernel,
                         cudaFuncAttributeMaxDynamicSharedMemorySize, GEMM_SMEM);
    cudaFuncSetAttribute(attn_mma_kernel,
                         cudaFuncAttributeMaxDynamicSharedMemorySize, ATTN_SMEM);

    dim3 tb(32, 8);
    // one-time splits
    split_kernel<<<(TOK * D_MODEL / 4 + 255) / 256, 256>>>(x, xh, xl, TOK * D_MODEL / 4);
    wsplit_t_kernel<<<dim3(D_MODEL / 32, D_MODEL / 32), tb>>>(Wq, wqth, wqtl, D_MODEL, D_MODEL);
    wsplit_t_kernel<<<dim3(KVD / 32, D_MODEL / 32), tb>>>(Wk, wkth, wktl, D_MODEL, KVD);
    wsplit_t_kernel<<<dim3(KVD / 32, D_MODEL / 32), tb>>>(Wv, wvth, wvtl, D_MODEL, KVD);
    wsplit_t_kernel<<<dim3(D_MODEL / 32, D_MODEL / 32), tb>>>(Wo, woth, wotl, D_MODEL, D_MODEL);

    // projections
    gemm_mma_kernel<<<dim3(D_MODEL / GBN, TOK / GBM), 256, GEMM_SMEM>>>(
        xh, xl, wqth, wqtl, q, TOK, D_MODEL, D_MODEL);
    gemm_mma_kernel<<<dim3(KVD / GBN, TOK / GBM), 256, GEMM_SMEM>>>(
        xh, xl, wkth, wktl, k, TOK, KVD, D_MODEL);
    gemm_mma_kernel<<<dim3(KVD / GBN, TOK / GBM), 256, GEMM_SMEM>>>(
        xh, xl, wvth, wvtl, v, TOK, KVD, D_MODEL);

    // rope + rms + split; V split+transpose
    rope_rms_split_kernel<<<(TOK * NH) / 8, 256>>>(q, qh, ql, cosp, sinp, NH);
    rope_rms_split_kernel<<<(TOK * NKV) / 8, 256>>>(k, kh, kl, cosp, sinp, NKV);
    vsplit_t_kernel<<<dim3(HD / 32, SEQ / 32, BATCH * NKV), tb>>>();

    // attention
    attn_mma_kernel<<<dim3(SEQ / 128, NH, BATCH), 256, ATTN_SMEM>>>();

    // output projection
    gemm_mma_kernel<<<dim3(D_MODEL / GBN, TOK / GBM), 256, GEMM_SMEM>>>(
        oh, ol, woth, wotl, out, TOK, D_MODEL, D_MODEL);
}